// round 13
// baseline (speedup 1.0000x reference)
#include <cuda_runtime.h>
#include <cuda_fp16.h>
#include <math.h>
#include <stdint.h>

// ---------------- problem constants ----------------
#define S_LEN 128
#define BATCH 32
#define HID   1024
#define EMB   1024
#define VOCAB 32000
#define SB    (S_LEN * BATCH)          // 4096
#define BH    (BATCH * HID)            // 32768
#define NBLK  256                      // persistent recurrence grid

// ---------------- scratch (device globals; no runtime alloc) ----------------
__device__ float  g_embeds[SB * EMB];      // [S*B, E] exact fp32
__device__ __half g_embeds_h[SB * EMB];    // fp16 copy (GEMM A operand)
__device__ float  g_xi1[SB * HID];
__device__ float  g_xf1[SB * HID];
__device__ float  g_xi2[SB * HID];
__device__ float  g_xf2[SB * HID];
__device__ float  g_lats1[SB * HID];       // layer-1 latent sequence (= l1_out)
__device__ __half g_lats1_h[SB * HID];
__device__ float  g_lats2[SB * HID];       // layer-2 latent sequence (= l2_out)
__device__ __half g_lats2_h[SB * HID];
__device__ float  g_part0[8 * BH];         // split-K partials, gate i
__device__ float  g_part1[8 * BH];         // split-K partials, gate f
__device__ __half g_h2o_h[(size_t)VOCAB * HID];   // 64MB fp16 weight copy
__device__ __half g_wx_h[4][HID * EMB];           // fp16 copies of Wxi,Wxf,Wxi2,Wxf2
__device__ unsigned int g_bar_count;
__device__ unsigned int g_bar_gen;

// ---------------- helpers ----------------
__device__ __forceinline__ void mma_f16(float c[4],
                                        uint32_t a0, uint32_t a1, uint32_t a2, uint32_t a3,
                                        uint32_t b0, uint32_t b1) {
    asm volatile(
        "mma.sync.aligned.m16n8k16.row.col.f32.f16.f16.f32 "
        "{%0,%1,%2,%3}, {%4,%5,%6,%7}, {%8,%9}, {%0,%1,%2,%3};"
        : "+f"(c[0]), "+f"(c[1]), "+f"(c[2]), "+f"(c[3])
        : "r"(a0), "r"(a1), "r"(a2), "r"(a3), "r"(b0), "r"(b1));
}

// fp16-accumulator MMA, zero C — caller promotes to fp32 immediately after.
__device__ __forceinline__ void mma_f16acc(uint32_t d[2],
                                           uint32_t a0, uint32_t a1, uint32_t a2, uint32_t a3,
                                           uint32_t b0, uint32_t b1) {
    asm volatile(
        "mma.sync.aligned.m16n8k16.row.col.f16.f16.f16.f16 "
        "{%0,%1}, {%2,%3,%4,%5}, {%6,%7}, {%8,%9};"
        : "=r"(d[0]), "=r"(d[1])
        : "r"(a0), "r"(a1), "r"(a2), "r"(a3), "r"(b0), "r"(b1),
          "r"(0u), "r"(0u));
}

__device__ __forceinline__ void cp_async16(void* smem_dst, const void* gsrc) {
    uint32_t s = (uint32_t)__cvta_generic_to_shared(smem_dst);
    asm volatile("cp.async.cg.shared.global [%0], [%1], 16;" :: "r"(s), "l"(gsrc));
}

// ---------------- fp16 conversion pre-pass ----------------
__global__ void to_f16_kernel(const float* __restrict__ src, __half* __restrict__ dst,
                              int n4) {
    int i = blockIdx.x * blockDim.x + threadIdx.x;
    if (i < n4) {
        float4 v = ((const float4*)src)[i];
        __half2* d = (__half2*)(dst + (size_t)i * 4);
        d[0] = __floats2half2_rn(v.x, v.y);
        d[1] = __floats2half2_rn(v.z, v.w);
    }
}

// ---------------- embedding gather (writes fp32 + fp16 copies) ----------------
__global__ void embed_gather(const int* __restrict__ word,
                             const float* __restrict__ emb,
                             float* __restrict__ out,
                             __half* __restrict__ out_h) {
    int row = blockIdx.x;                 // 0..4095 = s*B+b
    int w = word[row];
    float4 v = ((const float4*)(emb + (size_t)w * EMB))[threadIdx.x];
    ((float4*)(out + (size_t)row * EMB))[threadIdx.x] = v;
    __half2* d = (__half2*)(out_h + (size_t)row * EMB + (size_t)threadIdx.x * 4);
    d[0] = __floats2half2_rn(v.x, v.y);
    d[1] = __floats2half2_rn(v.z, v.w);
}

// ---------------- pipelined fp16 NT GEMM: C = A*B^T + bias -------------------
// fp16-accum MMA with immediate per-k16 fp32 promotion (half-rate-probe).
#define PSTAGES 3
#define HSTRIDE 40                       // halves per tile row (32 data + 8 pad)
#define HTILE   (128 * HSTRIDE)          // 5120 halves per tile
#define GEMM_SMEM (PSTAGES * 2 * HTILE * 2)   // 61440 bytes

__global__ __launch_bounds__(256, 2)
void gemm_f16_pipe(const __half* __restrict__ A, const __half* __restrict__ B,
                   const float* __restrict__ bias, float* __restrict__ C,
                   int M, int N, int K, int swap) {
    extern __shared__ __half smh[];
    __half* As = smh;                      // [PSTAGES][128][HSTRIDE]
    __half* Bs = smh + PSTAGES * HTILE;

    int tid = threadIdx.x;
    int bn = (swap ? blockIdx.y : blockIdx.x) * 128;
    int bm = (swap ? blockIdx.x : blockIdx.y) * 128;
    int wid = tid >> 5, lane = tid & 31;
    int wm = wid & 3;
    int wn = wid >> 2;
    int grp = lane >> 2;
    int tig = lane & 3;

    int r0 = tid >> 2, c0 = (tid & 3) << 3;      // chunk tid
    int r1 = r0 + 64, c1 = c0;                   // chunk tid+256
    const __half* Ab = A + (size_t)bm * K;
    const __half* Bb = B + (size_t)bn * K;

    float acc[2][8][4];
#pragma unroll
    for (int i = 0; i < 2; i++)
#pragma unroll
        for (int j = 0; j < 8; j++)
#pragma unroll
            for (int q = 0; q < 4; q++) acc[i][j][q] = 0.f;

    int KT = K >> 5;

#pragma unroll
    for (int s = 0; s < PSTAGES - 1; s++) {
        int k0 = s * 32;
        cp_async16(&As[s * HTILE + r0 * HSTRIDE + c0], Ab + (size_t)r0 * K + k0 + c0);
        cp_async16(&As[s * HTILE + r1 * HSTRIDE + c1], Ab + (size_t)r1 * K + k0 + c1);
        cp_async16(&Bs[s * HTILE + r0 * HSTRIDE + c0], Bb + (size_t)r0 * K + k0 + c0);
        cp_async16(&Bs[s * HTILE + r1 * HSTRIDE + c1], Bb + (size_t)r1 * K + k0 + c1);
        asm volatile("cp.async.commit_group;");
    }

    for (int kt = 0; kt < KT; kt++) {
        asm volatile("cp.async.wait_group %0;" :: "n"(PSTAGES - 2));
        __syncthreads();

        const __half* Ast = &As[(kt % PSTAGES) * HTILE];
        const __half* Bst = &Bs[(kt % PSTAGES) * HTILE];

#pragma unroll
        for (int ks = 0; ks < 2; ks++) {
            int koff = ks * 16 + 2 * tig;
            uint32_t af[2][4];
#pragma unroll
            for (int i = 0; i < 2; i++) {
                int mr = wm * 32 + i * 16 + grp;
                af[i][0] = *(const uint32_t*)&Ast[mr * HSTRIDE + koff];
                af[i][1] = *(const uint32_t*)&Ast[(mr + 8) * HSTRIDE + koff];
                af[i][2] = *(const uint32_t*)&Ast[mr * HSTRIDE + koff + 8];
                af[i][3] = *(const uint32_t*)&Ast[(mr + 8) * HSTRIDE + koff + 8];
            }
            uint32_t bf[8][2];
#pragma unroll
            for (int j = 0; j < 8; j++) {
                int nc = wn * 64 + j * 8 + grp;
                bf[j][0] = *(const uint32_t*)&Bst[nc * HSTRIDE + koff];
                bf[j][1] = *(const uint32_t*)&Bst[nc * HSTRIDE + koff + 8];
            }
#pragma unroll
            for (int i = 0; i < 2; i++)
#pragma unroll
                for (int j = 0; j < 8; j++) {
                    uint32_t d[2];
                    mma_f16acc(d, af[i][0], af[i][1], af[i][2], af[i][3],
                               bf[j][0], bf[j][1]);
                    float2 f0 = __half22float2(*(__half2*)&d[0]);
                    float2 f1 = __half22float2(*(__half2*)&d[1]);
                    acc[i][j][0] += f0.x;
                    acc[i][j][1] += f0.y;
                    acc[i][j][2] += f1.x;
                    acc[i][j][3] += f1.y;
                }
        }

        int nk = kt + PSTAGES - 1;
        if (nk < KT) {
            int st = nk % PSTAGES;
            int k0 = nk * 32;
            cp_async16(&As[st * HTILE + r0 * HSTRIDE + c0], Ab + (size_t)r0 * K + k0 + c0);
            cp_async16(&As[st * HTILE + r1 * HSTRIDE + c1], Ab + (size_t)r1 * K + k0 + c1);
            cp_async16(&Bs[st * HTILE + r0 * HSTRIDE + c0], Bb + (size_t)r0 * K + k0 + c0);
            cp_async16(&Bs[st * HTILE + r1 * HSTRIDE + c1], Bb + (size_t)r1 * K + k0 + c1);
        }
        asm volatile("cp.async.commit_group;");
    }

#pragma unroll
    for (int i = 0; i < 2; i++) {
        int row = bm + wm * 32 + i * 16 + grp;
#pragma unroll
        for (int j = 0; j < 8; j++) {
            int col = bn + wn * 64 + j * 8 + 2 * tig;
            float bsv0 = bias[col], bsv1 = bias[col + 1];
            float2 o0 = make_float2(acc[i][j][0] + bsv0, acc[i][j][1] + bsv1);
            float2 o1 = make_float2(acc[i][j][2] + bsv0, acc[i][j][3] + bsv1);
            *(float2*)(C + (size_t)row * N + col) = o0;
            *(float2*)(C + (size_t)(row + 8) * N + col) = o1;
        }
    }
}

// ---------------- software grid barrier (all NBLK blocks co-resident) --------
__device__ __forceinline__ void grid_barrier() {
    __syncthreads();
    if (threadIdx.x == 0) {
        volatile unsigned int* genp = &g_bar_gen;
        unsigned int gen = *genp;
        __threadfence();
        unsigned int rank = atomicAdd(&g_bar_count, 1u);
        if (rank == NBLK - 1) {
            g_bar_count = 0u;
            __threadfence();
            *genp = gen + 1u;
        } else {
            while (*genp == gen) { __nanosleep(32); }
        }
        __threadfence();
    }
    __syncthreads();
}

// ---------------- persistent recurrence v3 (R12-proven): fp16-split HMMA -----
#define RW 136                            // smem row stride (halves)
#define REC3_SMEM ((64 * RW + 64 * RW + 32 * RW + 32 * RW) * 2)   // 52224 B

__global__ __launch_bounds__(256)
void ran_recurrence3(const float* __restrict__ Wi, const float* __restrict__ Wf,
                     const float* __restrict__ xi, const float* __restrict__ xf,
                     const float* __restrict__ xseq,
                     const float* __restrict__ lat0,
                     float* __restrict__ lats,
                     __half* __restrict__ lats_h,
                     float* __restrict__ part0, float* __restrict__ part1,
                     float* __restrict__ igout, float* __restrict__ fgout) {
    extern __shared__ __half sh[];
    __half* sWhi = sh;                    // [64][RW]
    __half* sWlo = sh + 64 * RW;          // [64][RW]
    __half* sLhi = sh + 128 * RW;         // [32][RW]
    __half* sLlo = sh + 160 * RW;         // [32][RW]

    int tid = threadIdx.x;
    int gt = blockIdx.x & 31;
    int kc = blockIdx.x >> 5;
    int g0 = gt * 32;
    int k0 = kc * 128;
    int wid = tid >> 5, lane = tid & 31;
    int wm = wid & 3, wn = wid >> 2;
    int grp = lane >> 2, tig = lane & 3;

    // ---- load + split W once: 64 rows (32 gate-i + 32 gate-f) x 128 k ----
    for (int i = tid; i < 2048; i += 256) {         // 2048 float4 chunks
        int row = i >> 5, c4 = i & 31;
        const float* src = (row < 32)
            ? (Wi + (size_t)(g0 + row) * HID + k0 + c4 * 4)
            : (Wf + (size_t)(g0 + row - 32) * HID + k0 + c4 * 4);
        float4 v = *(const float4*)src;
        __half2 h0 = __floats2half2_rn(v.x, v.y);
        __half2 h1 = __floats2half2_rn(v.z, v.w);
        float2 f0 = __half22float2(h0), f1 = __half22float2(h1);
        __half2 l0 = __floats2half2_rn(v.x - f0.x, v.y - f0.y);
        __half2 l1 = __floats2half2_rn(v.z - f1.x, v.w - f1.y);
        int off = row * RW + c4 * 4;
        *(__half2*)&sWhi[off] = h0; *(__half2*)&sWhi[off + 2] = h1;
        *(__half2*)&sWlo[off] = l0; *(__half2*)&sWlo[off + 2] = l1;
    }

    const __half* Ahi = sWhi + (16 * wm + grp) * RW;
    const __half* Alo = sWlo + (16 * wm + grp) * RW;

    for (int s = 0; s < S_LEN; s++) {
        const float* latp = (s == 0) ? lat0 : (lats + (size_t)(s - 1) * BH);

        // ---- stage + split lat tile [32 b][128 k] ----
        for (int i = tid; i < 1024; i += 256) {
            int b = i >> 5, kq = i & 31;
            float4 v = __ldcg((const float4*)(latp + (size_t)b * HID + k0 + kq * 4));
            __half2 h0 = __floats2half2_rn(v.x, v.y);
            __half2 h1 = __floats2half2_rn(v.z, v.w);
            float2 f0 = __half22float2(h0), f1 = __half22float2(h1);
            __half2 l0 = __floats2half2_rn(v.x - f0.x, v.y - f0.y);
            __half2 l1 = __floats2half2_rn(v.z - f1.x, v.w - f1.y);
            int off = b * RW + kq * 4;
            *(__half2*)&sLhi[off] = h0; *(__half2*)&sLhi[off + 2] = h1;
            *(__half2*)&sLlo[off] = l0; *(__half2*)&sLlo[off + 2] = l1;
        }
        __syncthreads();

        // ---- split-K gate GEMM via HMMA: warp tile m16 x n16 (2 n-tiles) ----
        float acc[2][4];
#pragma unroll
        for (int jj = 0; jj < 2; jj++)
#pragma unroll
            for (int q = 0; q < 4; q++) acc[jj][q] = 0.f;

#pragma unroll
        for (int ks = 0; ks < 8; ks++) {
            int kb = ks * 16 + 2 * tig;
            uint32_t ah0 = *(const uint32_t*)&Ahi[kb];
            uint32_t ah1 = *(const uint32_t*)&Ahi[8 * RW + kb];
            uint32_t ah2 = *(const uint32_t*)&Ahi[kb + 8];
            uint32_t ah3 = *(const uint32_t*)&Ahi[8 * RW + kb + 8];
            uint32_t al0 = *(const uint32_t*)&Alo[kb];
            uint32_t al1 = *(const uint32_t*)&Alo[8 * RW + kb];
            uint32_t al2 = *(const uint32_t*)&Alo[kb + 8];
            uint32_t al3 = *(const uint32_t*)&Alo[8 * RW + kb + 8];
#pragma unroll
            for (int jj = 0; jj < 2; jj++) {
                int brow = (16 * wn + 8 * jj + grp) * RW;
                uint32_t bh0 = *(const uint32_t*)&sLhi[brow + kb];
                uint32_t bh1 = *(const uint32_t*)&sLhi[brow + kb + 8];
                uint32_t bl0 = *(const uint32_t*)&sLlo[brow + kb];
                uint32_t bl1 = *(const uint32_t*)&sLlo[brow + kb + 8];
                mma_f16(acc[jj], ah0, ah1, ah2, ah3, bh0, bh1);   // hi*hi
                mma_f16(acc[jj], al0, al1, al2, al3, bh0, bh1);   // lo*hi
                mma_f16(acc[jj], ah0, ah1, ah2, ah3, bl0, bl1);   // hi*lo
            }
        }

        // ---- write partials (same [kc][g*32+b] layout as R4) ----
        int row0 = 16 * wm + grp;
#pragma unroll
        for (int jj = 0; jj < 2; jj++) {
            int bcol = 16 * wn + 8 * jj + 2 * tig;
            {
                int r = row0;
                float* pp = (r < 32) ? part0 : part1;
                int gg = g0 + (r & 31);
                pp[kc * BH + gg * 32 + bcol]     = acc[jj][0];
                pp[kc * BH + gg * 32 + bcol + 1] = acc[jj][1];
            }
            {
                int r = row0 + 8;
                float* pp = (r < 32) ? part0 : part1;
                int gg = g0 + (r & 31);
                pp[kc * BH + gg * 32 + bcol]     = acc[jj][2];
                pp[kc * BH + gg * 32 + bcol + 1] = acc[jj][3];
            }
        }

        grid_barrier();

        // ---- epilogue: reduce + sigmoid + state update (R4-proven) ----
        if (tid < 128) {
            int p = blockIdx.x * 128 + tid;
            float ci = 0.f, cf = 0.f;
#pragma unroll
            for (int q = 0; q < 8; q++) {
                ci += __ldcg(&part0[q * BH + p]);
                cf += __ldcg(&part1[q * BH + p]);
            }
            int g = p >> 5, b = p & 31;
            int idx = b * HID + g;
            size_t sidx = (size_t)s * BH + idx;
            float ig = 1.f / (1.f + expf(-(ci + xi[sidx])));
            float fg = 1.f / (1.f + expf(-(cf + xf[sidx])));
            float nl = ig * xseq[sidx] + fg * __ldcg(latp + idx);
            lats[sidx] = nl;
            lats_h[sidx] = __float2half_rn(nl);
            if (s == S_LEN - 1 && igout) {
                igout[idx] = ig;
                fgout[idx] = fg;
            }
        }

        if (s != S_LEN - 1) grid_barrier();
    }
}

// ---------------- host orchestration ----------------
extern "C" void kernel_launch(void* const* d_in, const int* in_sizes, int n_in,
                              void* d_out, int out_size) {
    const int*   word    = (const int*)d_in[0];
    const float* latent0 = (const float*)d_in[1];
    const float* emb     = (const float*)d_in[2];
    const float* h2o_w   = (const float*)d_in[3];
    const float* h2o_b   = (const float*)d_in[4];
    const float* Whi     = (const float*)d_in[5];
    const float* Wxi_w   = (const float*)d_in[6];
    const float* Wxi_b   = (const float*)d_in[7];
    const float* Whf     = (const float*)d_in[8];
    const float* Wxf_w   = (const float*)d_in[9];
    const float* Wxf_b   = (const float*)d_in[10];
    const float* Whi2    = (const float*)d_in[11];
    const float* Wxi2_w  = (const float*)d_in[12];
    const float* Wxi2_b  = (const float*)d_in[13];
    const float* Whf2    = (const float*)d_in[14];
    const float* Wxf2_w  = (const float*)d_in[15];
    const float* Wxf2_b  = (const float*)d_in[16];
    float* out = (float*)d_out;

    float *embeds, *xi1, *xf1, *xi2, *xf2, *lats1, *lats2, *p0, *p1;
    __half *embeds_h, *lats1_h, *lats2_h, *h2o_h, *wx_h;
    cudaGetSymbolAddress((void**)&embeds, g_embeds);
    cudaGetSymbolAddress((void**)&embeds_h, g_embeds_h);
    cudaGetSymbolAddress((void**)&xi1, g_xi1);
    cudaGetSymbolAddress((void**)&xf1, g_xf1);
    cudaGetSymbolAddress((void**)&xi2, g_xi2);
    cudaGetSymbolAddress((void**)&xf2, g_xf2);
    cudaGetSymbolAddress((void**)&lats1, g_lats1);
    cudaGetSymbolAddress((void**)&lats1_h, g_lats1_h);
    cudaGetSymbolAddress((void**)&lats2, g_lats2);
    cudaGetSymbolAddress((void**)&lats2_h, g_lats2_h);
    cudaGetSymbolAddress((void**)&p0, g_part0);
    cudaGetSymbolAddress((void**)&p1, g_part1);
    cudaGetSymbolAddress((void**)&h2o_h, g_h2o_h);
    cudaGetSymbolAddress((void**)&wx_h, g_wx_h);

    static bool attr_done = false;
    if (!attr_done) {
        cudaFuncSetAttribute(ran_recurrence3,
                             cudaFuncAttributeMaxDynamicSharedMemorySize, REC3_SMEM);
        cudaFuncSetAttribute(gemm_f16_pipe,
                             cudaFuncAttributeMaxDynamicSharedMemorySize, GEMM_SMEM);
        attr_done = true;
    }

    // output layout (reference return order): latent | logits | ig_last | fg_last
    float* out_latent = out;
    float* out_logits = out + BH;
    float* out_ig     = out + (size_t)BH + (size_t)SB * VOCAB;
    float* out_fg     = out_ig + BH;

    __half* wxi_h  = wx_h;
    __half* wxf_h  = wx_h + (size_t)HID * EMB;
    __half* wxi2_h = wx_h + 2 * (size_t)HID * EMB;
    __half* wxf2_h = wx_h + 3 * (size_t)HID * EMB;

    // 0) fp16 pre-conversion of batched-GEMM weights
    {
        int n4w = (int)((size_t)VOCAB * HID / 4);
        to_f16_kernel<<<(n4w + 255) / 256, 256>>>(h2o_w, h2o_h, n4w);
        int n4 = HID * EMB / 4;
        to_f16_kernel<<<(n4 + 255) / 256, 256>>>(Wxi_w, wxi_h, n4);
        to_f16_kernel<<<(n4 + 255) / 256, 256>>>(Wxf_w, wxf_h, n4);
        to_f16_kernel<<<(n4 + 255) / 256, 256>>>(Wxi2_w, wxi2_h, n4);
        to_f16_kernel<<<(n4 + 255) / 256, 256>>>(Wxf2_w, wxf2_h, n4);
    }

    // 1) embedding gather (fp32 + fp16 copies)
    embed_gather<<<SB, 256>>>(word, emb, embeds, embeds_h);

    // 2) layer-1 input gate pre-activations (fp16 mma.sync)
    {
        dim3 grid(HID / 128, SB / 128);
        gemm_f16_pipe<<<grid, 256, GEMM_SMEM>>>(embeds_h, wxi_h, Wxi_b, xi1,
                                                SB, HID, EMB, 0);
        gemm_f16_pipe<<<grid, 256, GEMM_SMEM>>>(embeds_h, wxf_h, Wxf_b, xf1,
                                                SB, HID, EMB, 0);
    }

    // 3) layer-1 recurrence (persistent, fp16-split HMMA, fp32-class precision)
    ran_recurrence3<<<NBLK, 256, REC3_SMEM>>>(Whi, Whf, xi1, xf1, embeds, latent0,
                                              lats1, lats1_h, p0, p1,
                                              nullptr, nullptr);

    // 4) layer-2 input gate pre-activations (input = l1_out)
    {
        dim3 grid(HID / 128, SB / 128);
        gemm_f16_pipe<<<grid, 256, GEMM_SMEM>>>(lats1_h, wxi2_h, Wxi2_b, xi2,
                                                SB, HID, EMB, 0);
        gemm_f16_pipe<<<grid, 256, GEMM_SMEM>>>(lats1_h, wxf2_h, Wxf2_b, xf2,
                                                SB, HID, EMB, 0);
    }

    // 5) layer-2 recurrence (initial latent = layer-1 final latent)
    ran_recurrence3<<<NBLK, 256, REC3_SMEM>>>(Whi2, Whf2, xi2, xf2, lats1,
                                              lats1 + (size_t)(S_LEN - 1) * BH,
                                              lats2, lats2_h, p0, p1,
                                              out_ig, out_fg);

    // 6) final latent copy
    cudaMemcpyAsync(out_latent, lats2 + (size_t)(S_LEN - 1) * BH,
                    BH * sizeof(float), cudaMemcpyDeviceToDevice);

    // 7) logits = l2_out @ h2o_w^T + h2o_b  (fp16 mma.sync, m-fastest grid)
    {
        dim3 grid(SB / 128, VOCAB / 128);
        gemm_f16_pipe<<<grid, 256, GEMM_SMEM>>>(lats2_h, h2o_h, h2o_b, out_logits,
                                                SB, VOCAB, HID, 1);
    }

    (void)in_sizes; (void)n_in; (void)out_size;
}

// round 14
// speedup vs baseline: 1.0915x; 1.0915x over previous
#include <cuda_runtime.h>
#include <cuda_fp16.h>
#include <math.h>
#include <stdint.h>

// ---------------- problem constants ----------------
#define S_LEN 128
#define BATCH 32
#define HID   1024
#define EMB   1024
#define VOCAB 32000
#define SB    (S_LEN * BATCH)          // 4096
#define BH    (BATCH * HID)            // 32768
#define NBLK  256                      // persistent recurrence grid

// ---------------- scratch (device globals; no runtime alloc) ----------------
__device__ float  g_embeds[SB * EMB];      // [S*B, E] exact fp32
__device__ __half g_embeds_h[SB * EMB];    // fp16 copy (GEMM A operand)
__device__ float  g_xi1[SB * HID];
__device__ float  g_xf1[SB * HID];
__device__ float  g_xi2[SB * HID];
__device__ float  g_xf2[SB * HID];
__device__ float  g_lats1[SB * HID];       // layer-1 latent sequence (= l1_out)
__device__ __half g_lats1_h[SB * HID];
__device__ float  g_lats2[SB * HID];       // layer-2 latent sequence (= l2_out)
__device__ __half g_lats2_h[SB * HID];
__device__ float  g_part0[8 * BH];         // split-K partials, gate i
__device__ float  g_part1[8 * BH];         // split-K partials, gate f
__device__ __half g_h2o_h[(size_t)VOCAB * HID];   // 64MB fp16 weight copy
__device__ __half g_wx_h[4][HID * EMB];           // fp16 copies of Wxi,Wxf,Wxi2,Wxf2
__device__ unsigned int g_bar_count;
__device__ unsigned int g_bar_gen;

// ---------------- helpers ----------------
__device__ __forceinline__ void mma_f16(float c[4],
                                        uint32_t a0, uint32_t a1, uint32_t a2, uint32_t a3,
                                        uint32_t b0, uint32_t b1) {
    asm volatile(
        "mma.sync.aligned.m16n8k16.row.col.f32.f16.f16.f32 "
        "{%0,%1,%2,%3}, {%4,%5,%6,%7}, {%8,%9}, {%0,%1,%2,%3};"
        : "+f"(c[0]), "+f"(c[1]), "+f"(c[2]), "+f"(c[3])
        : "r"(a0), "r"(a1), "r"(a2), "r"(a3), "r"(b0), "r"(b1));
}

__device__ __forceinline__ void cp_async16(void* smem_dst, const void* gsrc) {
    uint32_t s = (uint32_t)__cvta_generic_to_shared(smem_dst);
    asm volatile("cp.async.cg.shared.global [%0], [%1], 16;" :: "r"(s), "l"(gsrc));
}

// ---------------- fp16 conversion pre-pass ----------------
__global__ void to_f16_kernel(const float* __restrict__ src, __half* __restrict__ dst,
                              int n4) {
    int i = blockIdx.x * blockDim.x + threadIdx.x;
    if (i < n4) {
        float4 v = ((const float4*)src)[i];
        __half2* d = (__half2*)(dst + (size_t)i * 4);
        d[0] = __floats2half2_rn(v.x, v.y);
        d[1] = __floats2half2_rn(v.z, v.w);
    }
}

// ---------------- embedding gather (writes fp32 + fp16 copies) ----------------
__global__ void embed_gather(const int* __restrict__ word,
                             const float* __restrict__ emb,
                             float* __restrict__ out,
                             __half* __restrict__ out_h) {
    int row = blockIdx.x;                 // 0..4095 = s*B+b
    int w = word[row];
    float4 v = ((const float4*)(emb + (size_t)w * EMB))[threadIdx.x];
    ((float4*)(out + (size_t)row * EMB))[threadIdx.x] = v;
    __half2* d = (__half2*)(out_h + (size_t)row * EMB + (size_t)threadIdx.x * 4);
    d[0] = __floats2half2_rn(v.x, v.y);
    d[1] = __floats2half2_rn(v.z, v.w);
}

// ---------------- pipelined fp16 NT GEMM (R12-proven): C = A*B^T + bias ------
#define PSTAGES 3
#define HSTRIDE 40                       // halves per tile row (32 data + 8 pad)
#define HTILE   (128 * HSTRIDE)          // 5120 halves per tile
#define GEMM_SMEM (PSTAGES * 2 * HTILE * 2)   // 61440 bytes

__global__ __launch_bounds__(256, 2)
void gemm_f16_pipe(const __half* __restrict__ A, const __half* __restrict__ B,
                   const float* __restrict__ bias, float* __restrict__ C,
                   int M, int N, int K, int swap) {
    extern __shared__ __half smh[];
    __half* As = smh;                      // [PSTAGES][128][HSTRIDE]
    __half* Bs = smh + PSTAGES * HTILE;

    int tid = threadIdx.x;
    int bn = (swap ? blockIdx.y : blockIdx.x) * 128;
    int bm = (swap ? blockIdx.x : blockIdx.y) * 128;
    int wid = tid >> 5, lane = tid & 31;
    int wm = wid & 3;
    int wn = wid >> 2;
    int grp = lane >> 2;
    int tig = lane & 3;

    int r0 = tid >> 2, c0 = (tid & 3) << 3;      // chunk tid
    int r1 = r0 + 64, c1 = c0;                   // chunk tid+256
    const __half* Ab = A + (size_t)bm * K;
    const __half* Bb = B + (size_t)bn * K;

    float acc[2][8][4];
#pragma unroll
    for (int i = 0; i < 2; i++)
#pragma unroll
        for (int j = 0; j < 8; j++)
#pragma unroll
            for (int q = 0; q < 4; q++) acc[i][j][q] = 0.f;

    int KT = K >> 5;

#pragma unroll
    for (int s = 0; s < PSTAGES - 1; s++) {
        int k0 = s * 32;
        cp_async16(&As[s * HTILE + r0 * HSTRIDE + c0], Ab + (size_t)r0 * K + k0 + c0);
        cp_async16(&As[s * HTILE + r1 * HSTRIDE + c1], Ab + (size_t)r1 * K + k0 + c1);
        cp_async16(&Bs[s * HTILE + r0 * HSTRIDE + c0], Bb + (size_t)r0 * K + k0 + c0);
        cp_async16(&Bs[s * HTILE + r1 * HSTRIDE + c1], Bb + (size_t)r1 * K + k0 + c1);
        asm volatile("cp.async.commit_group;");
    }

    for (int kt = 0; kt < KT; kt++) {
        asm volatile("cp.async.wait_group %0;" :: "n"(PSTAGES - 2));
        __syncthreads();

        const __half* Ast = &As[(kt % PSTAGES) * HTILE];
        const __half* Bst = &Bs[(kt % PSTAGES) * HTILE];

#pragma unroll
        for (int ks = 0; ks < 2; ks++) {
            int koff = ks * 16 + 2 * tig;
            uint32_t af[2][4];
#pragma unroll
            for (int i = 0; i < 2; i++) {
                int mr = wm * 32 + i * 16 + grp;
                af[i][0] = *(const uint32_t*)&Ast[mr * HSTRIDE + koff];
                af[i][1] = *(const uint32_t*)&Ast[(mr + 8) * HSTRIDE + koff];
                af[i][2] = *(const uint32_t*)&Ast[mr * HSTRIDE + koff + 8];
                af[i][3] = *(const uint32_t*)&Ast[(mr + 8) * HSTRIDE + koff + 8];
            }
            uint32_t bf[8][2];
#pragma unroll
            for (int j = 0; j < 8; j++) {
                int nc = wn * 64 + j * 8 + grp;
                bf[j][0] = *(const uint32_t*)&Bst[nc * HSTRIDE + koff];
                bf[j][1] = *(const uint32_t*)&Bst[nc * HSTRIDE + koff + 8];
            }
#pragma unroll
            for (int i = 0; i < 2; i++)
#pragma unroll
                for (int j = 0; j < 8; j++)
                    mma_f16(acc[i][j], af[i][0], af[i][1], af[i][2], af[i][3],
                            bf[j][0], bf[j][1]);
        }

        int nk = kt + PSTAGES - 1;
        if (nk < KT) {
            int st = nk % PSTAGES;
            int k0 = nk * 32;
            cp_async16(&As[st * HTILE + r0 * HSTRIDE + c0], Ab + (size_t)r0 * K + k0 + c0);
            cp_async16(&As[st * HTILE + r1 * HSTRIDE + c1], Ab + (size_t)r1 * K + k0 + c1);
            cp_async16(&Bs[st * HTILE + r0 * HSTRIDE + c0], Bb + (size_t)r0 * K + k0 + c0);
            cp_async16(&Bs[st * HTILE + r1 * HSTRIDE + c1], Bb + (size_t)r1 * K + k0 + c1);
        }
        asm volatile("cp.async.commit_group;");
    }

#pragma unroll
    for (int i = 0; i < 2; i++) {
        int row = bm + wm * 32 + i * 16 + grp;
#pragma unroll
        for (int j = 0; j < 8; j++) {
            int col = bn + wn * 64 + j * 8 + 2 * tig;
            float bsv0 = bias[col], bsv1 = bias[col + 1];
            float2 o0 = make_float2(acc[i][j][0] + bsv0, acc[i][j][1] + bsv1);
            float2 o1 = make_float2(acc[i][j][2] + bsv0, acc[i][j][3] + bsv1);
            *(float2*)(C + (size_t)row * N + col) = o0;
            *(float2*)(C + (size_t)(row + 8) * N + col) = o1;
        }
    }
}

// ---------------- software grid barrier (all NBLK blocks co-resident) --------
__device__ __forceinline__ void grid_barrier() {
    __syncthreads();
    if (threadIdx.x == 0) {
        volatile unsigned int* genp = &g_bar_gen;
        unsigned int gen = *genp;
        __threadfence();
        unsigned int rank = atomicAdd(&g_bar_count, 1u);
        if (rank == NBLK - 1) {
            g_bar_count = 0u;
            __threadfence();
            *genp = gen + 1u;
        } else {
            while (*genp == gen) { __nanosleep(32); }
        }
        __threadfence();
    }
    __syncthreads();
}

// ---------------- persistent recurrence v4: 2-term split HMMA ----------------
// Same skeleton as R12. preact = Whi*Lhi + Wlo*Lhi = W * fp16(lat): the W factor
// is error-free (hi+lo split), only lat is rounded to fp16 (rel ~2.4e-4, damped
// by sigmoid). Drops the third MMA and the lat-lo staging entirely.
#define RW 136                            // smem row stride (halves)
#define REC4_SMEM ((64 * RW + 64 * RW + 32 * RW) * 2)   // 43520 B

__global__ __launch_bounds__(256)
void ran_recurrence4(const float* __restrict__ Wi, const float* __restrict__ Wf,
                     const float* __restrict__ xi, const float* __restrict__ xf,
                     const float* __restrict__ xseq,
                     const float* __restrict__ lat0,
                     float* __restrict__ lats,
                     __half* __restrict__ lats_h,
                     float* __restrict__ part0, float* __restrict__ part1,
                     float* __restrict__ igout, float* __restrict__ fgout) {
    extern __shared__ __half sh[];
    __half* sWhi = sh;                    // [64][RW]
    __half* sWlo = sh + 64 * RW;          // [64][RW]
    __half* sLhi = sh + 128 * RW;         // [32][RW]

    int tid = threadIdx.x;
    int gt = blockIdx.x & 31;
    int kc = blockIdx.x >> 5;
    int g0 = gt * 32;
    int k0 = kc * 128;
    int wid = tid >> 5, lane = tid & 31;
    int wm = wid & 3, wn = wid >> 2;
    int grp = lane >> 2, tig = lane & 3;

    // ---- load + split W once: 64 rows (32 gate-i + 32 gate-f) x 128 k ----
    for (int i = tid; i < 2048; i += 256) {         // 2048 float4 chunks
        int row = i >> 5, c4 = i & 31;
        const float* src = (row < 32)
            ? (Wi + (size_t)(g0 + row) * HID + k0 + c4 * 4)
            : (Wf + (size_t)(g0 + row - 32) * HID + k0 + c4 * 4);
        float4 v = *(const float4*)src;
        __half2 h0 = __floats2half2_rn(v.x, v.y);
        __half2 h1 = __floats2half2_rn(v.z, v.w);
        float2 f0 = __half22float2(h0), f1 = __half22float2(h1);
        __half2 l0 = __floats2half2_rn(v.x - f0.x, v.y - f0.y);
        __half2 l1 = __floats2half2_rn(v.z - f1.x, v.w - f1.y);
        int off = row * RW + c4 * 4;
        *(__half2*)&sWhi[off] = h0; *(__half2*)&sWhi[off + 2] = h1;
        *(__half2*)&sWlo[off] = l0; *(__half2*)&sWlo[off + 2] = l1;
    }

    const __half* Ahi = sWhi + (16 * wm + grp) * RW;
    const __half* Alo = sWlo + (16 * wm + grp) * RW;

    for (int s = 0; s < S_LEN; s++) {
        const float* latp = (s == 0) ? lat0 : (lats + (size_t)(s - 1) * BH);

        // ---- stage lat tile [32 b][128 k] as fp16-hi only ----
        for (int i = tid; i < 1024; i += 256) {
            int b = i >> 5, kq = i & 31;
            float4 v = __ldcg((const float4*)(latp + (size_t)b * HID + k0 + kq * 4));
            int off = b * RW + kq * 4;
            *(__half2*)&sLhi[off]     = __floats2half2_rn(v.x, v.y);
            *(__half2*)&sLhi[off + 2] = __floats2half2_rn(v.z, v.w);
        }
        __syncthreads();

        // ---- split-K gate GEMM via HMMA: warp tile m16 x n16 (2 n-tiles) ----
        float acc[2][4];
#pragma unroll
        for (int jj = 0; jj < 2; jj++)
#pragma unroll
            for (int q = 0; q < 4; q++) acc[jj][q] = 0.f;

#pragma unroll
        for (int ks = 0; ks < 8; ks++) {
            int kb = ks * 16 + 2 * tig;
            uint32_t ah0 = *(const uint32_t*)&Ahi[kb];
            uint32_t ah1 = *(const uint32_t*)&Ahi[8 * RW + kb];
            uint32_t ah2 = *(const uint32_t*)&Ahi[kb + 8];
            uint32_t ah3 = *(const uint32_t*)&Ahi[8 * RW + kb + 8];
            uint32_t al0 = *(const uint32_t*)&Alo[kb];
            uint32_t al1 = *(const uint32_t*)&Alo[8 * RW + kb];
            uint32_t al2 = *(const uint32_t*)&Alo[kb + 8];
            uint32_t al3 = *(const uint32_t*)&Alo[8 * RW + kb + 8];
#pragma unroll
            for (int jj = 0; jj < 2; jj++) {
                int brow = (16 * wn + 8 * jj + grp) * RW;
                uint32_t bh0 = *(const uint32_t*)&sLhi[brow + kb];
                uint32_t bh1 = *(const uint32_t*)&sLhi[brow + kb + 8];
                mma_f16(acc[jj], ah0, ah1, ah2, ah3, bh0, bh1);   // Whi * Lhi
                mma_f16(acc[jj], al0, al1, al2, al3, bh0, bh1);   // Wlo * Lhi
            }
        }

        // ---- write partials (same [kc][g*32+b] layout as R4) ----
        int row0 = 16 * wm + grp;
#pragma unroll
        for (int jj = 0; jj < 2; jj++) {
            int bcol = 16 * wn + 8 * jj + 2 * tig;
            {
                int r = row0;
                float* pp = (r < 32) ? part0 : part1;
                int gg = g0 + (r & 31);
                pp[kc * BH + gg * 32 + bcol]     = acc[jj][0];
                pp[kc * BH + gg * 32 + bcol + 1] = acc[jj][1];
            }
            {
                int r = row0 + 8;
                float* pp = (r < 32) ? part0 : part1;
                int gg = g0 + (r & 31);
                pp[kc * BH + gg * 32 + bcol]     = acc[jj][2];
                pp[kc * BH + gg * 32 + bcol + 1] = acc[jj][3];
            }
        }

        grid_barrier();

        // ---- epilogue: reduce + sigmoid + state update (R4-proven) ----
        if (tid < 128) {
            int p = blockIdx.x * 128 + tid;
            float ci = 0.f, cf = 0.f;
#pragma unroll
            for (int q = 0; q < 8; q++) {
                ci += __ldcg(&part0[q * BH + p]);
                cf += __ldcg(&part1[q * BH + p]);
            }
            int g = p >> 5, b = p & 31;
            int idx = b * HID + g;
            size_t sidx = (size_t)s * BH + idx;
            float ig = 1.f / (1.f + expf(-(ci + xi[sidx])));
            float fg = 1.f / (1.f + expf(-(cf + xf[sidx])));
            float nl = ig * xseq[sidx] + fg * __ldcg(latp + idx);
            lats[sidx] = nl;
            lats_h[sidx] = __float2half_rn(nl);
            if (s == S_LEN - 1 && igout) {
                igout[idx] = ig;
                fgout[idx] = fg;
            }
        }

        if (s != S_LEN - 1) grid_barrier();
    }
}

// ---------------- host orchestration ----------------
extern "C" void kernel_launch(void* const* d_in, const int* in_sizes, int n_in,
                              void* d_out, int out_size) {
    const int*   word    = (const int*)d_in[0];
    const float* latent0 = (const float*)d_in[1];
    const float* emb     = (const float*)d_in[2];
    const float* h2o_w   = (const float*)d_in[3];
    const float* h2o_b   = (const float*)d_in[4];
    const float* Whi     = (const float*)d_in[5];
    const float* Wxi_w   = (const float*)d_in[6];
    const float* Wxi_b   = (const float*)d_in[7];
    const float* Whf     = (const float*)d_in[8];
    const float* Wxf_w   = (const float*)d_in[9];
    const float* Wxf_b   = (const float*)d_in[10];
    const float* Whi2    = (const float*)d_in[11];
    const float* Wxi2_w  = (const float*)d_in[12];
    const float* Wxi2_b  = (const float*)d_in[13];
    const float* Whf2    = (const float*)d_in[14];
    const float* Wxf2_w  = (const float*)d_in[15];
    const float* Wxf2_b  = (const float*)d_in[16];
    float* out = (float*)d_out;

    float *embeds, *xi1, *xf1, *xi2, *xf2, *lats1, *lats2, *p0, *p1;
    __half *embeds_h, *lats1_h, *lats2_h, *h2o_h, *wx_h;
    cudaGetSymbolAddress((void**)&embeds, g_embeds);
    cudaGetSymbolAddress((void**)&embeds_h, g_embeds_h);
    cudaGetSymbolAddress((void**)&xi1, g_xi1);
    cudaGetSymbolAddress((void**)&xf1, g_xf1);
    cudaGetSymbolAddress((void**)&xi2, g_xi2);
    cudaGetSymbolAddress((void**)&xf2, g_xf2);
    cudaGetSymbolAddress((void**)&lats1, g_lats1);
    cudaGetSymbolAddress((void**)&lats1_h, g_lats1_h);
    cudaGetSymbolAddress((void**)&lats2, g_lats2);
    cudaGetSymbolAddress((void**)&lats2_h, g_lats2_h);
    cudaGetSymbolAddress((void**)&p0, g_part0);
    cudaGetSymbolAddress((void**)&p1, g_part1);
    cudaGetSymbolAddress((void**)&h2o_h, g_h2o_h);
    cudaGetSymbolAddress((void**)&wx_h, g_wx_h);

    static bool attr_done = false;
    if (!attr_done) {
        cudaFuncSetAttribute(ran_recurrence4,
                             cudaFuncAttributeMaxDynamicSharedMemorySize, REC4_SMEM);
        cudaFuncSetAttribute(gemm_f16_pipe,
                             cudaFuncAttributeMaxDynamicSharedMemorySize, GEMM_SMEM);
        attr_done = true;
    }

    // output layout (reference return order): latent | logits | ig_last | fg_last
    float* out_latent = out;
    float* out_logits = out + BH;
    float* out_ig     = out + (size_t)BH + (size_t)SB * VOCAB;
    float* out_fg     = out_ig + BH;

    __half* wxi_h  = wx_h;
    __half* wxf_h  = wx_h + (size_t)HID * EMB;
    __half* wxi2_h = wx_h + 2 * (size_t)HID * EMB;
    __half* wxf2_h = wx_h + 3 * (size_t)HID * EMB;

    // 0) fp16 pre-conversion of batched-GEMM weights
    {
        int n4w = (int)((size_t)VOCAB * HID / 4);
        to_f16_kernel<<<(n4w + 255) / 256, 256>>>(h2o_w, h2o_h, n4w);
        int n4 = HID * EMB / 4;
        to_f16_kernel<<<(n4 + 255) / 256, 256>>>(Wxi_w, wxi_h, n4);
        to_f16_kernel<<<(n4 + 255) / 256, 256>>>(Wxf_w, wxf_h, n4);
        to_f16_kernel<<<(n4 + 255) / 256, 256>>>(Wxi2_w, wxi2_h, n4);
        to_f16_kernel<<<(n4 + 255) / 256, 256>>>(Wxf2_w, wxf2_h, n4);
    }

    // 1) embedding gather (fp32 + fp16 copies)
    embed_gather<<<SB, 256>>>(word, emb, embeds, embeds_h);

    // 2) layer-1 input gate pre-activations (fp16 mma.sync, f32 accum)
    {
        dim3 grid(HID / 128, SB / 128);
        gemm_f16_pipe<<<grid, 256, GEMM_SMEM>>>(embeds_h, wxi_h, Wxi_b, xi1,
                                                SB, HID, EMB, 0);
        gemm_f16_pipe<<<grid, 256, GEMM_SMEM>>>(embeds_h, wxf_h, Wxf_b, xf1,
                                                SB, HID, EMB, 0);
    }

    // 3) layer-1 recurrence (persistent, 2-term split HMMA)
    ran_recurrence4<<<NBLK, 256, REC4_SMEM>>>(Whi, Whf, xi1, xf1, embeds, latent0,
                                              lats1, lats1_h, p0, p1,
                                              nullptr, nullptr);

    // 4) layer-2 input gate pre-activations (input = l1_out)
    {
        dim3 grid(HID / 128, SB / 128);
        gemm_f16_pipe<<<grid, 256, GEMM_SMEM>>>(lats1_h, wxi2_h, Wxi2_b, xi2,
                                                SB, HID, EMB, 0);
        gemm_f16_pipe<<<grid, 256, GEMM_SMEM>>>(lats1_h, wxf2_h, Wxf2_b, xf2,
                                                SB, HID, EMB, 0);
    }

    // 5) layer-2 recurrence (initial latent = layer-1 final latent)
    ran_recurrence4<<<NBLK, 256, REC4_SMEM>>>(Whi2, Whf2, xi2, xf2, lats1,
                                              lats1 + (size_t)(S_LEN - 1) * BH,
                                              lats2, lats2_h, p0, p1,
                                              out_ig, out_fg);

    // 6) final latent copy
    cudaMemcpyAsync(out_latent, lats2 + (size_t)(S_LEN - 1) * BH,
                    BH * sizeof(float), cudaMemcpyDeviceToDevice);

    // 7) logits = l2_out @ h2o_w^T + h2o_b  (fp16 mma.sync, m-fastest grid)
    {
        dim3 grid(SB / 128, VOCAB / 128);
        gemm_f16_pipe<<<grid, 256, GEMM_SMEM>>>(lats2_h, h2o_h, h2o_b, out_logits,
                                                SB, VOCAB, HID, 1);
    }

    (void)in_sizes; (void)n_in; (void)out_size;
}

// round 15
// speedup vs baseline: 1.1625x; 1.0651x over previous
#include <cuda_runtime.h>
#include <cuda_fp16.h>
#include <math.h>
#include <stdint.h>

// ---------------- problem constants ----------------
#define S_LEN 128
#define BATCH 32
#define HID   1024
#define EMB   1024
#define VOCAB 32000
#define SB    (S_LEN * BATCH)          // 4096
#define BH    (BATCH * HID)            // 32768
#define NBLK  256                      // persistent recurrence grid

// ---------------- scratch (device globals; no runtime alloc) ----------------
__device__ float  g_embeds[SB * EMB];      // [S*B, E] exact fp32
__device__ __half g_embeds_h[SB * EMB];    // fp16 copy (GEMM A operand)
__device__ float  g_xi1[SB * HID];
__device__ float  g_xf1[SB * HID];
__device__ float  g_xi2[SB * HID];
__device__ float  g_xf2[SB * HID];
__device__ float  g_lats1[SB * HID];       // layer-1 latent sequence (= l1_out)
__device__ __half g_lats1_h[SB * HID];
__device__ float  g_lats2[SB * HID];       // layer-2 latent sequence (= l2_out)
__device__ __half g_lats2_h[SB * HID];
__device__ float  g_part0[8 * BH];         // split-K partials, gate i
__device__ float  g_part1[8 * BH];         // split-K partials, gate f
__device__ __half g_h2o_h[(size_t)VOCAB * HID];   // 64MB fp16 weight copy
__device__ __half g_wx_h[4][HID * EMB];           // fp16 copies of Wxi,Wxf,Wxi2,Wxf2
__device__ unsigned int g_bar_count;
__device__ unsigned int g_bar_gen;

// ---------------- helpers ----------------
__device__ __forceinline__ void mma_f16(float c[4],
                                        uint32_t a0, uint32_t a1, uint32_t a2, uint32_t a3,
                                        uint32_t b0, uint32_t b1) {
    asm volatile(
        "mma.sync.aligned.m16n8k16.row.col.f32.f16.f16.f32 "
        "{%0,%1,%2,%3}, {%4,%5,%6,%7}, {%8,%9}, {%0,%1,%2,%3};"
        : "+f"(c[0]), "+f"(c[1]), "+f"(c[2]), "+f"(c[3])
        : "r"(a0), "r"(a1), "r"(a2), "r"(a3), "r"(b0), "r"(b1));
}

__device__ __forceinline__ void cp_async16(void* smem_dst, const void* gsrc) {
    uint32_t s = (uint32_t)__cvta_generic_to_shared(smem_dst);
    asm volatile("cp.async.cg.shared.global [%0], [%1], 16;" :: "r"(s), "l"(gsrc));
}

// ---------------- fp16 conversion pre-pass ----------------
__global__ void to_f16_kernel(const float* __restrict__ src, __half* __restrict__ dst,
                              int n4) {
    int i = blockIdx.x * blockDim.x + threadIdx.x;
    if (i < n4) {
        float4 v = ((const float4*)src)[i];
        __half2* d = (__half2*)(dst + (size_t)i * 4);
        d[0] = __floats2half2_rn(v.x, v.y);
        d[1] = __floats2half2_rn(v.z, v.w);
    }
}

// ---------------- embedding gather (writes fp32 + fp16 copies) ----------------
__global__ void embed_gather(const int* __restrict__ word,
                             const float* __restrict__ emb,
                             float* __restrict__ out,
                             __half* __restrict__ out_h) {
    int row = blockIdx.x;                 // 0..4095 = s*B+b
    int w = word[row];
    float4 v = ((const float4*)(emb + (size_t)w * EMB))[threadIdx.x];
    ((float4*)(out + (size_t)row * EMB))[threadIdx.x] = v;
    __half2* d = (__half2*)(out_h + (size_t)row * EMB + (size_t)threadIdx.x * 4);
    d[0] = __floats2half2_rn(v.x, v.y);
    d[1] = __floats2half2_rn(v.z, v.w);
}

// ---------------- pipelined fp16 NT GEMM (R12-proven): C = A*B^T + bias ------
#define PSTAGES 3
#define HSTRIDE 40                       // halves per tile row (32 data + 8 pad)
#define HTILE   (128 * HSTRIDE)          // 5120 halves per tile
#define GEMM_SMEM (PSTAGES * 2 * HTILE * 2)   // 61440 bytes

__global__ __launch_bounds__(256, 2)
void gemm_f16_pipe(const __half* __restrict__ A, const __half* __restrict__ B,
                   const float* __restrict__ bias, float* __restrict__ C,
                   int M, int N, int K, int swap) {
    extern __shared__ __half smh[];
    __half* As = smh;                      // [PSTAGES][128][HSTRIDE]
    __half* Bs = smh + PSTAGES * HTILE;

    int tid = threadIdx.x;
    int bn = (swap ? blockIdx.y : blockIdx.x) * 128;
    int bm = (swap ? blockIdx.x : blockIdx.y) * 128;
    int wid = tid >> 5, lane = tid & 31;
    int wm = wid & 3;
    int wn = wid >> 2;
    int grp = lane >> 2;
    int tig = lane & 3;

    int r0 = tid >> 2, c0 = (tid & 3) << 3;      // chunk tid
    int r1 = r0 + 64, c1 = c0;                   // chunk tid+256
    const __half* Ab = A + (size_t)bm * K;
    const __half* Bb = B + (size_t)bn * K;

    float acc[2][8][4];
#pragma unroll
    for (int i = 0; i < 2; i++)
#pragma unroll
        for (int j = 0; j < 8; j++)
#pragma unroll
            for (int q = 0; q < 4; q++) acc[i][j][q] = 0.f;

    int KT = K >> 5;

#pragma unroll
    for (int s = 0; s < PSTAGES - 1; s++) {
        int k0 = s * 32;
        cp_async16(&As[s * HTILE + r0 * HSTRIDE + c0], Ab + (size_t)r0 * K + k0 + c0);
        cp_async16(&As[s * HTILE + r1 * HSTRIDE + c1], Ab + (size_t)r1 * K + k0 + c1);
        cp_async16(&Bs[s * HTILE + r0 * HSTRIDE + c0], Bb + (size_t)r0 * K + k0 + c0);
        cp_async16(&Bs[s * HTILE + r1 * HSTRIDE + c1], Bb + (size_t)r1 * K + k0 + c1);
        asm volatile("cp.async.commit_group;");
    }

    for (int kt = 0; kt < KT; kt++) {
        asm volatile("cp.async.wait_group %0;" :: "n"(PSTAGES - 2));
        __syncthreads();

        const __half* Ast = &As[(kt % PSTAGES) * HTILE];
        const __half* Bst = &Bs[(kt % PSTAGES) * HTILE];

#pragma unroll
        for (int ks = 0; ks < 2; ks++) {
            int koff = ks * 16 + 2 * tig;
            uint32_t af[2][4];
#pragma unroll
            for (int i = 0; i < 2; i++) {
                int mr = wm * 32 + i * 16 + grp;
                af[i][0] = *(const uint32_t*)&Ast[mr * HSTRIDE + koff];
                af[i][1] = *(const uint32_t*)&Ast[(mr + 8) * HSTRIDE + koff];
                af[i][2] = *(const uint32_t*)&Ast[mr * HSTRIDE + koff + 8];
                af[i][3] = *(const uint32_t*)&Ast[(mr + 8) * HSTRIDE + koff + 8];
            }
            uint32_t bf[8][2];
#pragma unroll
            for (int j = 0; j < 8; j++) {
                int nc = wn * 64 + j * 8 + grp;
                bf[j][0] = *(const uint32_t*)&Bst[nc * HSTRIDE + koff];
                bf[j][1] = *(const uint32_t*)&Bst[nc * HSTRIDE + koff + 8];
            }
#pragma unroll
            for (int i = 0; i < 2; i++)
#pragma unroll
                for (int j = 0; j < 8; j++)
                    mma_f16(acc[i][j], af[i][0], af[i][1], af[i][2], af[i][3],
                            bf[j][0], bf[j][1]);
        }

        int nk = kt + PSTAGES - 1;
        if (nk < KT) {
            int st = nk % PSTAGES;
            int k0 = nk * 32;
            cp_async16(&As[st * HTILE + r0 * HSTRIDE + c0], Ab + (size_t)r0 * K + k0 + c0);
            cp_async16(&As[st * HTILE + r1 * HSTRIDE + c1], Ab + (size_t)r1 * K + k0 + c1);
            cp_async16(&Bs[st * HTILE + r0 * HSTRIDE + c0], Bb + (size_t)r0 * K + k0 + c0);
            cp_async16(&Bs[st * HTILE + r1 * HSTRIDE + c1], Bb + (size_t)r1 * K + k0 + c1);
        }
        asm volatile("cp.async.commit_group;");
    }

#pragma unroll
    for (int i = 0; i < 2; i++) {
        int row = bm + wm * 32 + i * 16 + grp;
#pragma unroll
        for (int j = 0; j < 8; j++) {
            int col = bn + wn * 64 + j * 8 + 2 * tig;
            float bsv0 = bias[col], bsv1 = bias[col + 1];
            float2 o0 = make_float2(acc[i][j][0] + bsv0, acc[i][j][1] + bsv1);
            float2 o1 = make_float2(acc[i][j][2] + bsv0, acc[i][j][3] + bsv1);
            *(float2*)(C + (size_t)row * N + col) = o0;
            *(float2*)(C + (size_t)(row + 8) * N + col) = o1;
        }
    }
}

// ---------------- software grid barrier (all NBLK blocks co-resident) --------
__device__ __forceinline__ void grid_barrier() {
    __syncthreads();
    if (threadIdx.x == 0) {
        volatile unsigned int* genp = &g_bar_gen;
        unsigned int gen = *genp;
        __threadfence();
        unsigned int rank = atomicAdd(&g_bar_count, 1u);
        if (rank == NBLK - 1) {
            g_bar_count = 0u;
            __threadfence();
            *genp = gen + 1u;
        } else {
            while (*genp == gen) { __nanosleep(16); }
        }
        __threadfence();
    }
    __syncthreads();
}

// ---------------- persistent recurrence v5: latency-trimmed ------------------
// R4 skeleton (256 blocks = 32 gt x 8 kc, 2 grid barriers/step). 2-term split
// HMMA (R14-proven). New: fp16-shadow staging (bit-identical), register-carried
// latent state, epilogue operand prefetch, __expf sigmoid.
#define RW 136                            // smem row stride (halves)
#define REC5_SMEM ((64 * RW + 64 * RW + 32 * RW) * 2)   // 43520 B

__global__ __launch_bounds__(256)
void ran_recurrence5(const float* __restrict__ Wi, const float* __restrict__ Wf,
                     const float* __restrict__ xi, const float* __restrict__ xf,
                     const float* __restrict__ xseq,
                     const float* __restrict__ lat0,
                     float* __restrict__ lats,
                     __half* __restrict__ lats_h,
                     float* __restrict__ part0, float* __restrict__ part1,
                     float* __restrict__ igout, float* __restrict__ fgout) {
    extern __shared__ __half sh[];
    __half* sWhi = sh;                    // [64][RW]
    __half* sWlo = sh + 64 * RW;          // [64][RW]
    __half* sLhi = sh + 128 * RW;         // [32][RW]

    int tid = threadIdx.x;
    int gt = blockIdx.x & 31;
    int kc = blockIdx.x >> 5;
    int g0 = gt * 32;
    int k0 = kc * 128;
    int wid = tid >> 5, lane = tid & 31;
    int wm = wid & 3, wn = wid >> 2;
    int grp = lane >> 2, tig = lane & 3;

    // ---- load + split W once: 64 rows (32 gate-i + 32 gate-f) x 128 k ----
    for (int i = tid; i < 2048; i += 256) {         // 2048 float4 chunks
        int row = i >> 5, c4 = i & 31;
        const float* src = (row < 32)
            ? (Wi + (size_t)(g0 + row) * HID + k0 + c4 * 4)
            : (Wf + (size_t)(g0 + row - 32) * HID + k0 + c4 * 4);
        float4 v = *(const float4*)src;
        __half2 h0 = __floats2half2_rn(v.x, v.y);
        __half2 h1 = __floats2half2_rn(v.z, v.w);
        float2 f0 = __half22float2(h0), f1 = __half22float2(h1);
        __half2 l0 = __floats2half2_rn(v.x - f0.x, v.y - f0.y);
        __half2 l1 = __floats2half2_rn(v.z - f1.x, v.w - f1.y);
        int off = row * RW + c4 * 4;
        *(__half2*)&sWhi[off] = h0; *(__half2*)&sWhi[off + 2] = h1;
        *(__half2*)&sWlo[off] = l0; *(__half2*)&sWlo[off + 2] = l1;
    }

    const __half* Ahi = sWhi + (16 * wm + grp) * RW;
    const __half* Alo = sWlo + (16 * wm + grp) * RW;

    // epilogue thread->output mapping is constant across steps
    int p = blockIdx.x * 128 + tid;       // valid for tid < 128
    int eg = p >> 5, eb = p & 31;
    int eidx = eb * HID + eg;
    float lstate = 0.f;
    if (tid < 128) lstate = __ldcg(lat0 + eidx);   // register-carried latent

    for (int s = 0; s < S_LEN; s++) {
        // ---- stage lat tile [32 b][128 k] as fp16 ----
        if (s == 0) {
            for (int i = tid; i < 1024; i += 256) {
                int b = i >> 5, kq = i & 31;
                float4 v = __ldcg((const float4*)(lat0 + (size_t)b * HID + k0 + kq * 4));
                int off = b * RW + kq * 4;
                *(__half2*)&sLhi[off]     = __floats2half2_rn(v.x, v.y);
                *(__half2*)&sLhi[off + 2] = __floats2half2_rn(v.z, v.w);
            }
        } else {
            const __half* lsrc = lats_h + (size_t)(s - 1) * BH;
            for (int i = tid; i < 512; i += 256) {       // 512 x 16B chunks
                int b = i >> 4, kq = i & 15;
                uint4 v = __ldcg((const uint4*)(lsrc + (size_t)b * HID + k0 + kq * 8));
                *(uint4*)&sLhi[b * RW + kq * 8] = v;
            }
        }

        // ---- prefetch epilogue operands (independent of partials/barrier) ----
        float pre_xi = 0.f, pre_xf = 0.f, pre_x = 0.f;
        size_t sidx = (size_t)s * BH + eidx;
        if (tid < 128) {
            pre_xi = __ldcg(xi + sidx);
            pre_xf = __ldcg(xf + sidx);
            pre_x  = __ldcg(xseq + sidx);
        }
        __syncthreads();

        // ---- split-K gate GEMM via HMMA: warp tile m16 x n16 (2 n-tiles) ----
        float acc[2][4];
#pragma unroll
        for (int jj = 0; jj < 2; jj++)
#pragma unroll
            for (int q = 0; q < 4; q++) acc[jj][q] = 0.f;

#pragma unroll
        for (int ks = 0; ks < 8; ks++) {
            int kb = ks * 16 + 2 * tig;
            uint32_t ah0 = *(const uint32_t*)&Ahi[kb];
            uint32_t ah1 = *(const uint32_t*)&Ahi[8 * RW + kb];
            uint32_t ah2 = *(const uint32_t*)&Ahi[kb + 8];
            uint32_t ah3 = *(const uint32_t*)&Ahi[8 * RW + kb + 8];
            uint32_t al0 = *(const uint32_t*)&Alo[kb];
            uint32_t al1 = *(const uint32_t*)&Alo[8 * RW + kb];
            uint32_t al2 = *(const uint32_t*)&Alo[kb + 8];
            uint32_t al3 = *(const uint32_t*)&Alo[8 * RW + kb + 8];
#pragma unroll
            for (int jj = 0; jj < 2; jj++) {
                int brow = (16 * wn + 8 * jj + grp) * RW;
                uint32_t bh0 = *(const uint32_t*)&sLhi[brow + kb];
                uint32_t bh1 = *(const uint32_t*)&sLhi[brow + kb + 8];
                mma_f16(acc[jj], ah0, ah1, ah2, ah3, bh0, bh1);   // Whi * Lhi
                mma_f16(acc[jj], al0, al1, al2, al3, bh0, bh1);   // Wlo * Lhi
            }
        }

        // ---- write partials (same [kc][g*32+b] layout as R4) ----
        int row0 = 16 * wm + grp;
#pragma unroll
        for (int jj = 0; jj < 2; jj++) {
            int bcol = 16 * wn + 8 * jj + 2 * tig;
            {
                int r = row0;
                float* pp = (r < 32) ? part0 : part1;
                int gg = g0 + (r & 31);
                pp[kc * BH + gg * 32 + bcol]     = acc[jj][0];
                pp[kc * BH + gg * 32 + bcol + 1] = acc[jj][1];
            }
            {
                int r = row0 + 8;
                float* pp = (r < 32) ? part0 : part1;
                int gg = g0 + (r & 31);
                pp[kc * BH + gg * 32 + bcol]     = acc[jj][2];
                pp[kc * BH + gg * 32 + bcol + 1] = acc[jj][3];
            }
        }

        grid_barrier();

        // ---- epilogue: reduce + sigmoid + state update ----
        if (tid < 128) {
            float ci = 0.f, cf = 0.f;
#pragma unroll
            for (int q = 0; q < 8; q++) {
                ci += __ldcg(&part0[q * BH + p]);
                cf += __ldcg(&part1[q * BH + p]);
            }
            float ig = 1.f / (1.f + __expf(-(ci + pre_xi)));
            float fg = 1.f / (1.f + __expf(-(cf + pre_xf)));
            float nl = ig * pre_x + fg * lstate;
            lstate = nl;
            lats[sidx] = nl;
            lats_h[sidx] = __float2half_rn(nl);
            if (s == S_LEN - 1 && igout) {
                igout[eidx] = ig;
                fgout[eidx] = fg;
            }
        }

        if (s != S_LEN - 1) grid_barrier();
    }
}

// ---------------- host orchestration ----------------
extern "C" void kernel_launch(void* const* d_in, const int* in_sizes, int n_in,
                              void* d_out, int out_size) {
    const int*   word    = (const int*)d_in[0];
    const float* latent0 = (const float*)d_in[1];
    const float* emb     = (const float*)d_in[2];
    const float* h2o_w   = (const float*)d_in[3];
    const float* h2o_b   = (const float*)d_in[4];
    const float* Whi     = (const float*)d_in[5];
    const float* Wxi_w   = (const float*)d_in[6];
    const float* Wxi_b   = (const float*)d_in[7];
    const float* Whf     = (const float*)d_in[8];
    const float* Wxf_w   = (const float*)d_in[9];
    const float* Wxf_b   = (const float*)d_in[10];
    const float* Whi2    = (const float*)d_in[11];
    const float* Wxi2_w  = (const float*)d_in[12];
    const float* Wxi2_b  = (const float*)d_in[13];
    const float* Whf2    = (const float*)d_in[14];
    const float* Wxf2_w  = (const float*)d_in[15];
    const float* Wxf2_b  = (const float*)d_in[16];
    float* out = (float*)d_out;

    float *embeds, *xi1, *xf1, *xi2, *xf2, *lats1, *lats2, *p0, *p1;
    __half *embeds_h, *lats1_h, *lats2_h, *h2o_h, *wx_h;
    cudaGetSymbolAddress((void**)&embeds, g_embeds);
    cudaGetSymbolAddress((void**)&embeds_h, g_embeds_h);
    cudaGetSymbolAddress((void**)&xi1, g_xi1);
    cudaGetSymbolAddress((void**)&xf1, g_xf1);
    cudaGetSymbolAddress((void**)&xi2, g_xi2);
    cudaGetSymbolAddress((void**)&xf2, g_xf2);
    cudaGetSymbolAddress((void**)&lats1, g_lats1);
    cudaGetSymbolAddress((void**)&lats1_h, g_lats1_h);
    cudaGetSymbolAddress((void**)&lats2, g_lats2);
    cudaGetSymbolAddress((void**)&lats2_h, g_lats2_h);
    cudaGetSymbolAddress((void**)&p0, g_part0);
    cudaGetSymbolAddress((void**)&p1, g_part1);
    cudaGetSymbolAddress((void**)&h2o_h, g_h2o_h);
    cudaGetSymbolAddress((void**)&wx_h, g_wx_h);

    static bool attr_done = false;
    if (!attr_done) {
        cudaFuncSetAttribute(ran_recurrence5,
                             cudaFuncAttributeMaxDynamicSharedMemorySize, REC5_SMEM);
        cudaFuncSetAttribute(gemm_f16_pipe,
                             cudaFuncAttributeMaxDynamicSharedMemorySize, GEMM_SMEM);
        attr_done = true;
    }

    // output layout (reference return order): latent | logits | ig_last | fg_last
    float* out_latent = out;
    float* out_logits = out + BH;
    float* out_ig     = out + (size_t)BH + (size_t)SB * VOCAB;
    float* out_fg     = out_ig + BH;

    __half* wxi_h  = wx_h;
    __half* wxf_h  = wx_h + (size_t)HID * EMB;
    __half* wxi2_h = wx_h + 2 * (size_t)HID * EMB;
    __half* wxf2_h = wx_h + 3 * (size_t)HID * EMB;

    // 0) fp16 pre-conversion of batched-GEMM weights
    {
        int n4w = (int)((size_t)VOCAB * HID / 4);
        to_f16_kernel<<<(n4w + 255) / 256, 256>>>(h2o_w, h2o_h, n4w);
        int n4 = HID * EMB / 4;
        to_f16_kernel<<<(n4 + 255) / 256, 256>>>(Wxi_w, wxi_h, n4);
        to_f16_kernel<<<(n4 + 255) / 256, 256>>>(Wxf_w, wxf_h, n4);
        to_f16_kernel<<<(n4 + 255) / 256, 256>>>(Wxi2_w, wxi2_h, n4);
        to_f16_kernel<<<(n4 + 255) / 256, 256>>>(Wxf2_w, wxf2_h, n4);
    }

    // 1) embedding gather (fp32 + fp16 copies)
    embed_gather<<<SB, 256>>>(word, emb, embeds, embeds_h);

    // 2) layer-1 input gate pre-activations (fp16 mma.sync, f32 accum)
    {
        dim3 grid(HID / 128, SB / 128);
        gemm_f16_pipe<<<grid, 256, GEMM_SMEM>>>(embeds_h, wxi_h, Wxi_b, xi1,
                                                SB, HID, EMB, 0);
        gemm_f16_pipe<<<grid, 256, GEMM_SMEM>>>(embeds_h, wxf_h, Wxf_b, xf1,
                                                SB, HID, EMB, 0);
    }

    // 3) layer-1 recurrence (persistent, 2-term split HMMA, latency-trimmed)
    ran_recurrence5<<<NBLK, 256, REC5_SMEM>>>(Whi, Whf, xi1, xf1, embeds, latent0,
                                              lats1, lats1_h, p0, p1,
                                              nullptr, nullptr);

    // 4) layer-2 input gate pre-activations (input = l1_out)
    {
        dim3 grid(HID / 128, SB / 128);
        gemm_f16_pipe<<<grid, 256, GEMM_SMEM>>>(lats1_h, wxi2_h, Wxi2_b, xi2,
                                                SB, HID, EMB, 0);
        gemm_f16_pipe<<<grid, 256, GEMM_SMEM>>>(lats1_h, wxf2_h, Wxf2_b, xf2,
                                                SB, HID, EMB, 0);
    }

    // 5) layer-2 recurrence (initial latent = layer-1 final latent)
    ran_recurrence5<<<NBLK, 256, REC5_SMEM>>>(Whi2, Whf2, xi2, xf2, lats1,
                                              lats1 + (size_t)(S_LEN - 1) * BH,
                                              lats2, lats2_h, p0, p1,
                                              out_ig, out_fg);

    // 6) final latent copy
    cudaMemcpyAsync(out_latent, lats2 + (size_t)(S_LEN - 1) * BH,
                    BH * sizeof(float), cudaMemcpyDeviceToDevice);

    // 7) logits = l2_out @ h2o_w^T + h2o_b  (fp16 mma.sync, m-fastest grid)
    {
        dim3 grid(SB / 128, VOCAB / 128);
        gemm_f16_pipe<<<grid, 256, GEMM_SMEM>>>(lats2_h, h2o_h, h2o_b, out_logits,
                                                SB, VOCAB, HID, 1);
    }

    (void)in_sizes; (void)n_in; (void)out_size;
}

// round 16
// speedup vs baseline: 1.1630x; 1.0004x over previous
#include <cuda_runtime.h>
#include <cuda_fp16.h>
#include <math.h>
#include <stdint.h>

// ---------------- problem constants ----------------
#define S_LEN 128
#define BATCH 32
#define HID   1024
#define EMB   1024
#define VOCAB 32000
#define SB    (S_LEN * BATCH)          // 4096
#define BH    (BATCH * HID)            // 32768
#define NBLK  256                      // persistent recurrence grid

// ---------------- scratch (device globals; no runtime alloc) ----------------
__device__ float  g_embeds[SB * EMB];      // [S*B, E] exact fp32
__device__ __half g_embeds_h[SB * EMB];    // fp16 copy (GEMM A operand)
__device__ float  g_xi1[SB * HID];
__device__ float  g_xf1[SB * HID];
__device__ float  g_xi2[SB * HID];
__device__ float  g_xf2[SB * HID];
__device__ float  g_lats1[SB * HID];       // layer-1 latent sequence (= l1_out)
__device__ __half g_lats1_h[SB * HID];
__device__ float  g_lats2[SB * HID];       // layer-2 latent sequence (= l2_out)
__device__ __half g_lats2_h[SB * HID];
__device__ float  g_part0[8 * BH];         // split-K partials, gate i
__device__ float  g_part1[8 * BH];         // split-K partials, gate f
__device__ __half g_h2o_h[(size_t)VOCAB * HID];   // 64MB fp16 weight copy
__device__ __half g_wx_h[4][HID * EMB];           // fp16 copies of Wxi,Wxf,Wxi2,Wxf2
__device__ unsigned int g_bar_count;
__device__ unsigned int g_bar_gen;

// ---------------- helpers ----------------
__device__ __forceinline__ void mma_f16(float c[4],
                                        uint32_t a0, uint32_t a1, uint32_t a2, uint32_t a3,
                                        uint32_t b0, uint32_t b1) {
    asm volatile(
        "mma.sync.aligned.m16n8k16.row.col.f32.f16.f16.f32 "
        "{%0,%1,%2,%3}, {%4,%5,%6,%7}, {%8,%9}, {%0,%1,%2,%3};"
        : "+f"(c[0]), "+f"(c[1]), "+f"(c[2]), "+f"(c[3])
        : "r"(a0), "r"(a1), "r"(a2), "r"(a3), "r"(b0), "r"(b1));
}

__device__ __forceinline__ void cp_async16(void* smem_dst, const void* gsrc) {
    uint32_t s = (uint32_t)__cvta_generic_to_shared(smem_dst);
    asm volatile("cp.async.cg.shared.global [%0], [%1], 16;" :: "r"(s), "l"(gsrc));
}

__device__ __forceinline__ uint2 f4_to_h4(float4 v) {
    __half2 h0 = __floats2half2_rn(v.x, v.y);
    __half2 h1 = __floats2half2_rn(v.z, v.w);
    uint2 u;
    u.x = *(uint32_t*)&h0;
    u.y = *(uint32_t*)&h1;
    return u;
}

// ---------------- fp16 conversion pre-pass (MLP-4) ----------------
__global__ void to_f16_kernel(const float* __restrict__ src, __half* __restrict__ dst,
                              int n4) {
    int base = blockIdx.x * (blockDim.x * 4) + threadIdx.x;
    float4 v[4];
    int idx[4];
#pragma unroll
    for (int k = 0; k < 4; k++) {
        idx[k] = base + k * blockDim.x;
        if (idx[k] < n4) v[k] = ((const float4*)src)[idx[k]];
    }
#pragma unroll
    for (int k = 0; k < 4; k++) {
        if (idx[k] < n4) ((uint2*)dst)[idx[k]] = f4_to_h4(v[k]);
    }
}

// ---------------- embedding gather (MLP-4, fp32 + fp16 copies) ---------------
// grid = SB/4 blocks x 256 threads; 64 threads per row, 4 chunks per thread.
__global__ void embed_gather(const int* __restrict__ word,
                             const float* __restrict__ emb,
                             float* __restrict__ out,
                             __half* __restrict__ out_h) {
    int r = blockIdx.x * 4 + (threadIdx.x >> 6);
    int c = threadIdx.x & 63;
    int w = word[r];
    const float4* src = (const float4*)(emb + (size_t)w * EMB);
    float4* dst = (float4*)(out + (size_t)r * EMB);
    uint2* dsth = (uint2*)(out_h + (size_t)r * EMB);
    float4 v[4];
#pragma unroll
    for (int k = 0; k < 4; k++) v[k] = src[c + k * 64];
#pragma unroll
    for (int k = 0; k < 4; k++) {
        dst[c + k * 64] = v[k];
        dsth[c + k * 64] = f4_to_h4(v[k]);
    }
}

// ---------------- pipelined fp16 NT GEMM (R12-proven): C = A*B^T + bias ------
#define PSTAGES 3
#define HSTRIDE 40                       // halves per tile row (32 data + 8 pad)
#define HTILE   (128 * HSTRIDE)          // 5120 halves per tile
#define GEMM_SMEM (PSTAGES * 2 * HTILE * 2)   // 61440 bytes

__global__ __launch_bounds__(256, 2)
void gemm_f16_pipe(const __half* __restrict__ A, const __half* __restrict__ B,
                   const float* __restrict__ bias, float* __restrict__ C,
                   int M, int N, int K, int swap) {
    extern __shared__ __half smh[];
    __half* As = smh;                      // [PSTAGES][128][HSTRIDE]
    __half* Bs = smh + PSTAGES * HTILE;

    int tid = threadIdx.x;
    int bn = (swap ? blockIdx.y : blockIdx.x) * 128;
    int bm = (swap ? blockIdx.x : blockIdx.y) * 128;
    int wid = tid >> 5, lane = tid & 31;
    int wm = wid & 3;
    int wn = wid >> 2;
    int grp = lane >> 2;
    int tig = lane & 3;

    int r0 = tid >> 2, c0 = (tid & 3) << 3;      // chunk tid
    int r1 = r0 + 64, c1 = c0;                   // chunk tid+256
    const __half* Ab = A + (size_t)bm * K;
    const __half* Bb = B + (size_t)bn * K;

    float acc[2][8][4];
#pragma unroll
    for (int i = 0; i < 2; i++)
#pragma unroll
        for (int j = 0; j < 8; j++)
#pragma unroll
            for (int q = 0; q < 4; q++) acc[i][j][q] = 0.f;

    int KT = K >> 5;

#pragma unroll
    for (int s = 0; s < PSTAGES - 1; s++) {
        int k0 = s * 32;
        cp_async16(&As[s * HTILE + r0 * HSTRIDE + c0], Ab + (size_t)r0 * K + k0 + c0);
        cp_async16(&As[s * HTILE + r1 * HSTRIDE + c1], Ab + (size_t)r1 * K + k0 + c1);
        cp_async16(&Bs[s * HTILE + r0 * HSTRIDE + c0], Bb + (size_t)r0 * K + k0 + c0);
        cp_async16(&Bs[s * HTILE + r1 * HSTRIDE + c1], Bb + (size_t)r1 * K + k0 + c1);
        asm volatile("cp.async.commit_group;");
    }

    for (int kt = 0; kt < KT; kt++) {
        asm volatile("cp.async.wait_group %0;" :: "n"(PSTAGES - 2));
        __syncthreads();

        const __half* Ast = &As[(kt % PSTAGES) * HTILE];
        const __half* Bst = &Bs[(kt % PSTAGES) * HTILE];

#pragma unroll
        for (int ks = 0; ks < 2; ks++) {
            int koff = ks * 16 + 2 * tig;
            uint32_t af[2][4];
#pragma unroll
            for (int i = 0; i < 2; i++) {
                int mr = wm * 32 + i * 16 + grp;
                af[i][0] = *(const uint32_t*)&Ast[mr * HSTRIDE + koff];
                af[i][1] = *(const uint32_t*)&Ast[(mr + 8) * HSTRIDE + koff];
                af[i][2] = *(const uint32_t*)&Ast[mr * HSTRIDE + koff + 8];
                af[i][3] = *(const uint32_t*)&Ast[(mr + 8) * HSTRIDE + koff + 8];
            }
            uint32_t bf[8][2];
#pragma unroll
            for (int j = 0; j < 8; j++) {
                int nc = wn * 64 + j * 8 + grp;
                bf[j][0] = *(const uint32_t*)&Bst[nc * HSTRIDE + koff];
                bf[j][1] = *(const uint32_t*)&Bst[nc * HSTRIDE + koff + 8];
            }
#pragma unroll
            for (int i = 0; i < 2; i++)
#pragma unroll
                for (int j = 0; j < 8; j++)
                    mma_f16(acc[i][j], af[i][0], af[i][1], af[i][2], af[i][3],
                            bf[j][0], bf[j][1]);
        }

        int nk = kt + PSTAGES - 1;
        if (nk < KT) {
            int st = nk % PSTAGES;
            int k0 = nk * 32;
            cp_async16(&As[st * HTILE + r0 * HSTRIDE + c0], Ab + (size_t)r0 * K + k0 + c0);
            cp_async16(&As[st * HTILE + r1 * HSTRIDE + c1], Ab + (size_t)r1 * K + k0 + c1);
            cp_async16(&Bs[st * HTILE + r0 * HSTRIDE + c0], Bb + (size_t)r0 * K + k0 + c0);
            cp_async16(&Bs[st * HTILE + r1 * HSTRIDE + c1], Bb + (size_t)r1 * K + k0 + c1);
        }
        asm volatile("cp.async.commit_group;");
    }

#pragma unroll
    for (int i = 0; i < 2; i++) {
        int row = bm + wm * 32 + i * 16 + grp;
#pragma unroll
        for (int j = 0; j < 8; j++) {
            int col = bn + wn * 64 + j * 8 + 2 * tig;
            float bsv0 = bias[col], bsv1 = bias[col + 1];
            float2 o0 = make_float2(acc[i][j][0] + bsv0, acc[i][j][1] + bsv1);
            float2 o1 = make_float2(acc[i][j][2] + bsv0, acc[i][j][3] + bsv1);
            *(float2*)(C + (size_t)row * N + col) = o0;
            *(float2*)(C + (size_t)(row + 8) * N + col) = o1;
        }
    }
}

// ---------------- software grid barrier (all NBLK blocks co-resident) --------
__device__ __forceinline__ void grid_barrier() {
    __syncthreads();
    if (threadIdx.x == 0) {
        volatile unsigned int* genp = &g_bar_gen;
        unsigned int gen = *genp;
        __threadfence();
        unsigned int rank = atomicAdd(&g_bar_count, 1u);
        if (rank == NBLK - 1) {
            g_bar_count = 0u;
            __threadfence();
            *genp = gen + 1u;
        } else {
            while (*genp == gen) { __nanosleep(16); }
        }
        __threadfence();
    }
    __syncthreads();
}

// ---------------- persistent recurrence v5 (R15-proven) ----------------------
#define RW 136                            // smem row stride (halves)
#define REC5_SMEM ((64 * RW + 64 * RW + 32 * RW) * 2)   // 43520 B

__global__ __launch_bounds__(256)
void ran_recurrence5(const float* __restrict__ Wi, const float* __restrict__ Wf,
                     const float* __restrict__ xi, const float* __restrict__ xf,
                     const float* __restrict__ xseq,
                     const float* __restrict__ lat0,
                     float* __restrict__ lats,
                     __half* __restrict__ lats_h,
                     float* __restrict__ part0, float* __restrict__ part1,
                     float* __restrict__ igout, float* __restrict__ fgout) {
    extern __shared__ __half sh[];
    __half* sWhi = sh;                    // [64][RW]
    __half* sWlo = sh + 64 * RW;          // [64][RW]
    __half* sLhi = sh + 128 * RW;         // [32][RW]

    int tid = threadIdx.x;
    int gt = blockIdx.x & 31;
    int kc = blockIdx.x >> 5;
    int g0 = gt * 32;
    int k0 = kc * 128;
    int wid = tid >> 5, lane = tid & 31;
    int wm = wid & 3, wn = wid >> 2;
    int grp = lane >> 2, tig = lane & 3;

    // ---- load + split W once: 64 rows (32 gate-i + 32 gate-f) x 128 k ----
    for (int i = tid; i < 2048; i += 256) {         // 2048 float4 chunks
        int row = i >> 5, c4 = i & 31;
        const float* src = (row < 32)
            ? (Wi + (size_t)(g0 + row) * HID + k0 + c4 * 4)
            : (Wf + (size_t)(g0 + row - 32) * HID + k0 + c4 * 4);
        float4 v = *(const float4*)src;
        __half2 h0 = __floats2half2_rn(v.x, v.y);
        __half2 h1 = __floats2half2_rn(v.z, v.w);
        float2 f0 = __half22float2(h0), f1 = __half22float2(h1);
        __half2 l0 = __floats2half2_rn(v.x - f0.x, v.y - f0.y);
        __half2 l1 = __floats2half2_rn(v.z - f1.x, v.w - f1.y);
        int off = row * RW + c4 * 4;
        *(__half2*)&sWhi[off] = h0; *(__half2*)&sWhi[off + 2] = h1;
        *(__half2*)&sWlo[off] = l0; *(__half2*)&sWlo[off + 2] = l1;
    }

    const __half* Ahi = sWhi + (16 * wm + grp) * RW;
    const __half* Alo = sWlo + (16 * wm + grp) * RW;

    // epilogue thread->output mapping is constant across steps
    int p = blockIdx.x * 128 + tid;       // valid for tid < 128
    int eg = p >> 5, eb = p & 31;
    int eidx = eb * HID + eg;
    float lstate = 0.f;
    if (tid < 128) lstate = __ldcg(lat0 + eidx);   // register-carried latent

    for (int s = 0; s < S_LEN; s++) {
        // ---- stage lat tile [32 b][128 k] as fp16 ----
        if (s == 0) {
            for (int i = tid; i < 1024; i += 256) {
                int b = i >> 5, kq = i & 31;
                float4 v = __ldcg((const float4*)(lat0 + (size_t)b * HID + k0 + kq * 4));
                int off = b * RW + kq * 4;
                *(__half2*)&sLhi[off]     = __floats2half2_rn(v.x, v.y);
                *(__half2*)&sLhi[off + 2] = __floats2half2_rn(v.z, v.w);
            }
        } else {
            const __half* lsrc = lats_h + (size_t)(s - 1) * BH;
            for (int i = tid; i < 512; i += 256) {       // 512 x 16B chunks
                int b = i >> 4, kq = i & 15;
                uint4 v = __ldcg((const uint4*)(lsrc + (size_t)b * HID + k0 + kq * 8));
                *(uint4*)&sLhi[b * RW + kq * 8] = v;
            }
        }

        // ---- prefetch epilogue operands (independent of partials/barrier) ----
        float pre_xi = 0.f, pre_xf = 0.f, pre_x = 0.f;
        size_t sidx = (size_t)s * BH + eidx;
        if (tid < 128) {
            pre_xi = __ldcg(xi + sidx);
            pre_xf = __ldcg(xf + sidx);
            pre_x  = __ldcg(xseq + sidx);
        }
        __syncthreads();

        // ---- split-K gate GEMM via HMMA: warp tile m16 x n16 (2 n-tiles) ----
        float acc[2][4];
#pragma unroll
        for (int jj = 0; jj < 2; jj++)
#pragma unroll
            for (int q = 0; q < 4; q++) acc[jj][q] = 0.f;

#pragma unroll
        for (int ks = 0; ks < 8; ks++) {
            int kb = ks * 16 + 2 * tig;
            uint32_t ah0 = *(const uint32_t*)&Ahi[kb];
            uint32_t ah1 = *(const uint32_t*)&Ahi[8 * RW + kb];
            uint32_t ah2 = *(const uint32_t*)&Ahi[kb + 8];
            uint32_t ah3 = *(const uint32_t*)&Ahi[8 * RW + kb + 8];
            uint32_t al0 = *(const uint32_t*)&Alo[kb];
            uint32_t al1 = *(const uint32_t*)&Alo[8 * RW + kb];
            uint32_t al2 = *(const uint32_t*)&Alo[kb + 8];
            uint32_t al3 = *(const uint32_t*)&Alo[8 * RW + kb + 8];
#pragma unroll
            for (int jj = 0; jj < 2; jj++) {
                int brow = (16 * wn + 8 * jj + grp) * RW;
                uint32_t bh0 = *(const uint32_t*)&sLhi[brow + kb];
                uint32_t bh1 = *(const uint32_t*)&sLhi[brow + kb + 8];
                mma_f16(acc[jj], ah0, ah1, ah2, ah3, bh0, bh1);   // Whi * Lhi
                mma_f16(acc[jj], al0, al1, al2, al3, bh0, bh1);   // Wlo * Lhi
            }
        }

        // ---- write partials (same [kc][g*32+b] layout as R4) ----
        int row0 = 16 * wm + grp;
#pragma unroll
        for (int jj = 0; jj < 2; jj++) {
            int bcol = 16 * wn + 8 * jj + 2 * tig;
            {
                int r = row0;
                float* pp = (r < 32) ? part0 : part1;
                int gg = g0 + (r & 31);
                pp[kc * BH + gg * 32 + bcol]     = acc[jj][0];
                pp[kc * BH + gg * 32 + bcol + 1] = acc[jj][1];
            }
            {
                int r = row0 + 8;
                float* pp = (r < 32) ? part0 : part1;
                int gg = g0 + (r & 31);
                pp[kc * BH + gg * 32 + bcol]     = acc[jj][2];
                pp[kc * BH + gg * 32 + bcol + 1] = acc[jj][3];
            }
        }

        grid_barrier();

        // ---- epilogue: reduce + sigmoid + state update ----
        if (tid < 128) {
            float ci = 0.f, cf = 0.f;
#pragma unroll
            for (int q = 0; q < 8; q++) {
                ci += __ldcg(&part0[q * BH + p]);
                cf += __ldcg(&part1[q * BH + p]);
            }
            float ig = 1.f / (1.f + __expf(-(ci + pre_xi)));
            float fg = 1.f / (1.f + __expf(-(cf + pre_xf)));
            float nl = ig * pre_x + fg * lstate;
            lstate = nl;
            lats[sidx] = nl;
            lats_h[sidx] = __float2half_rn(nl);
            if (s == S_LEN - 1 && igout) {
                igout[eidx] = ig;
                fgout[eidx] = fg;
            }
        }

        if (s != S_LEN - 1) grid_barrier();
    }
}

// ---------------- host orchestration ----------------
extern "C" void kernel_launch(void* const* d_in, const int* in_sizes, int n_in,
                              void* d_out, int out_size) {
    const int*   word    = (const int*)d_in[0];
    const float* latent0 = (const float*)d_in[1];
    const float* emb     = (const float*)d_in[2];
    const float* h2o_w   = (const float*)d_in[3];
    const float* h2o_b   = (const float*)d_in[4];
    const float* Whi     = (const float*)d_in[5];
    const float* Wxi_w   = (const float*)d_in[6];
    const float* Wxi_b   = (const float*)d_in[7];
    const float* Whf     = (const float*)d_in[8];
    const float* Wxf_w   = (const float*)d_in[9];
    const float* Wxf_b   = (const float*)d_in[10];
    const float* Whi2    = (const float*)d_in[11];
    const float* Wxi2_w  = (const float*)d_in[12];
    const float* Wxi2_b  = (const float*)d_in[13];
    const float* Whf2    = (const float*)d_in[14];
    const float* Wxf2_w  = (const float*)d_in[15];
    const float* Wxf2_b  = (const float*)d_in[16];
    float* out = (float*)d_out;

    float *embeds, *xi1, *xf1, *xi2, *xf2, *lats1, *lats2, *p0, *p1;
    __half *embeds_h, *lats1_h, *lats2_h, *h2o_h, *wx_h;
    cudaGetSymbolAddress((void**)&embeds, g_embeds);
    cudaGetSymbolAddress((void**)&embeds_h, g_embeds_h);
    cudaGetSymbolAddress((void**)&xi1, g_xi1);
    cudaGetSymbolAddress((void**)&xf1, g_xf1);
    cudaGetSymbolAddress((void**)&xi2, g_xi2);
    cudaGetSymbolAddress((void**)&xf2, g_xf2);
    cudaGetSymbolAddress((void**)&lats1, g_lats1);
    cudaGetSymbolAddress((void**)&lats1_h, g_lats1_h);
    cudaGetSymbolAddress((void**)&lats2, g_lats2);
    cudaGetSymbolAddress((void**)&lats2_h, g_lats2_h);
    cudaGetSymbolAddress((void**)&p0, g_part0);
    cudaGetSymbolAddress((void**)&p1, g_part1);
    cudaGetSymbolAddress((void**)&h2o_h, g_h2o_h);
    cudaGetSymbolAddress((void**)&wx_h, g_wx_h);

    static bool attr_done = false;
    if (!attr_done) {
        cudaFuncSetAttribute(ran_recurrence5,
                             cudaFuncAttributeMaxDynamicSharedMemorySize, REC5_SMEM);
        cudaFuncSetAttribute(gemm_f16_pipe,
                             cudaFuncAttributeMaxDynamicSharedMemorySize, GEMM_SMEM);
        attr_done = true;
    }

    // output layout (reference return order): latent | logits | ig_last | fg_last
    float* out_latent = out;
    float* out_logits = out + BH;
    float* out_ig     = out + (size_t)BH + (size_t)SB * VOCAB;
    float* out_fg     = out_ig + BH;

    __half* wxi_h  = wx_h;
    __half* wxf_h  = wx_h + (size_t)HID * EMB;
    __half* wxi2_h = wx_h + 2 * (size_t)HID * EMB;
    __half* wxf2_h = wx_h + 3 * (size_t)HID * EMB;

    // 0) fp16 pre-conversion of batched-GEMM weights (MLP-4 convert kernels)
    {
        int n4w = (int)((size_t)VOCAB * HID / 4);
        to_f16_kernel<<<(n4w + 1023) / 1024, 256>>>(h2o_w, h2o_h, n4w);
        int n4 = HID * EMB / 4;
        to_f16_kernel<<<(n4 + 1023) / 1024, 256>>>(Wxi_w, wxi_h, n4);
        to_f16_kernel<<<(n4 + 1023) / 1024, 256>>>(Wxf_w, wxf_h, n4);
        to_f16_kernel<<<(n4 + 1023) / 1024, 256>>>(Wxi2_w, wxi2_h, n4);
        to_f16_kernel<<<(n4 + 1023) / 1024, 256>>>(Wxf2_w, wxf2_h, n4);
    }

    // 1) embedding gather (fp32 + fp16 copies, 4 rows/block)
    embed_gather<<<SB / 4, 256>>>(word, emb, embeds, embeds_h);

    // 2) layer-1 input gate pre-activations (fp16 mma.sync, f32 accum)
    {
        dim3 grid(HID / 128, SB / 128);
        gemm_f16_pipe<<<grid, 256, GEMM_SMEM>>>(embeds_h, wxi_h, Wxi_b, xi1,
                                                SB, HID, EMB, 0);
        gemm_f16_pipe<<<grid, 256, GEMM_SMEM>>>(embeds_h, wxf_h, Wxf_b, xf1,
                                                SB, HID, EMB, 0);
    }

    // 3) layer-1 recurrence (persistent, 2-term split HMMA, latency-trimmed)
    ran_recurrence5<<<NBLK, 256, REC5_SMEM>>>(Whi, Whf, xi1, xf1, embeds, latent0,
                                              lats1, lats1_h, p0, p1,
                                              nullptr, nullptr);

    // 4) layer-2 input gate pre-activations (input = l1_out)
    {
        dim3 grid(HID / 128, SB / 128);
        gemm_f16_pipe<<<grid, 256, GEMM_SMEM>>>(lats1_h, wxi2_h, Wxi2_b, xi2,
                                                SB, HID, EMB, 0);
        gemm_f16_pipe<<<grid, 256, GEMM_SMEM>>>(lats1_h, wxf2_h, Wxf2_b, xf2,
                                                SB, HID, EMB, 0);
    }

    // 5) layer-2 recurrence (initial latent = layer-1 final latent)
    ran_recurrence5<<<NBLK, 256, REC5_SMEM>>>(Whi2, Whf2, xi2, xf2, lats1,
                                              lats1 + (size_t)(S_LEN - 1) * BH,
                                              lats2, lats2_h, p0, p1,
                                              out_ig, out_fg);

    // 6) final latent copy
    cudaMemcpyAsync(out_latent, lats2 + (size_t)(S_LEN - 1) * BH,
                    BH * sizeof(float), cudaMemcpyDeviceToDevice);

    // 7) logits = l2_out @ h2o_w^T + h2o_b  (fp16 mma.sync, m-fastest grid)
    {
        dim3 grid(SB / 128, VOCAB / 128);
        gemm_f16_pipe<<<grid, 256, GEMM_SMEM>>>(lats2_h, h2o_h, h2o_b, out_logits,
                                                SB, VOCAB, HID, 1);
    }

    (void)in_sizes; (void)n_in; (void)out_size;
}

// round 17
// speedup vs baseline: 1.1810x; 1.0154x over previous
#include <cuda_runtime.h>
#include <cuda_fp16.h>
#include <math.h>
#include <stdint.h>

// ---------------- problem constants ----------------
#define S_LEN 128
#define BATCH 32
#define HID   1024
#define EMB   1024
#define VOCAB 32000
#define SB    (S_LEN * BATCH)          // 4096
#define BH    (BATCH * HID)            // 32768
#define NBLK  256                      // persistent recurrence grid

// ---------------- scratch (device globals; no runtime alloc) ----------------
__device__ float  g_embeds[SB * EMB];      // [S*B, E] exact fp32
__device__ __half g_embeds_h[SB * EMB];    // fp16 copy (GEMM A operand)
__device__ float  g_xi1[SB * HID];
__device__ float  g_xf1[SB * HID];
__device__ float  g_xi2[SB * HID];
__device__ float  g_xf2[SB * HID];
__device__ float  g_lats1[SB * HID];       // layer-1 latent sequence (= l1_out)
__device__ __half g_lats1_h[SB * HID];
__device__ float  g_lats2[SB * HID];       // layer-2 latent sequence (= l2_out)
__device__ __half g_lats2_h[SB * HID];
__device__ float  g_part0[8 * BH];         // split-K partials, gate i
__device__ float  g_part1[8 * BH];         // split-K partials, gate f
__device__ __half g_h2o_h[(size_t)VOCAB * HID];   // 64MB fp16 weight copy
__device__ __half g_wx_h[4][HID * EMB];           // fp16 copies of Wxi,Wxf,Wxi2,Wxf2
__device__ unsigned int g_bar_count;
__device__ unsigned int g_bar_gen;

// ---------------- helpers ----------------
__device__ __forceinline__ void mma_f16(float c[4],
                                        uint32_t a0, uint32_t a1, uint32_t a2, uint32_t a3,
                                        uint32_t b0, uint32_t b1) {
    asm volatile(
        "mma.sync.aligned.m16n8k16.row.col.f32.f16.f16.f32 "
        "{%0,%1,%2,%3}, {%4,%5,%6,%7}, {%8,%9}, {%0,%1,%2,%3};"
        : "+f"(c[0]), "+f"(c[1]), "+f"(c[2]), "+f"(c[3])
        : "r"(a0), "r"(a1), "r"(a2), "r"(a3), "r"(b0), "r"(b1));
}

__device__ __forceinline__ void cp_async16(void* smem_dst, const void* gsrc) {
    uint32_t s = (uint32_t)__cvta_generic_to_shared(smem_dst);
    asm volatile("cp.async.cg.shared.global [%0], [%1], 16;" :: "r"(s), "l"(gsrc));
}

__device__ __forceinline__ uint2 f4_to_h4(float4 v) {
    __half2 h0 = __floats2half2_rn(v.x, v.y);
    __half2 h1 = __floats2half2_rn(v.z, v.w);
    uint2 u;
    u.x = *(uint32_t*)&h0;
    u.y = *(uint32_t*)&h1;
    return u;
}

// ---------------- fp16 conversion pre-pass (MLP-4) ----------------
__global__ void to_f16_kernel(const float* __restrict__ src, __half* __restrict__ dst,
                              int n4) {
    int base = blockIdx.x * (blockDim.x * 4) + threadIdx.x;
    float4 v[4];
    int idx[4];
#pragma unroll
    for (int k = 0; k < 4; k++) {
        idx[k] = base + k * blockDim.x;
        if (idx[k] < n4) v[k] = ((const float4*)src)[idx[k]];
    }
#pragma unroll
    for (int k = 0; k < 4; k++) {
        if (idx[k] < n4) ((uint2*)dst)[idx[k]] = f4_to_h4(v[k]);
    }
}

// ---------------- embedding gather (MLP-4, fp32 + fp16 copies) ---------------
__global__ void embed_gather(const int* __restrict__ word,
                             const float* __restrict__ emb,
                             float* __restrict__ out,
                             __half* __restrict__ out_h) {
    int r = blockIdx.x * 4 + (threadIdx.x >> 6);
    int c = threadIdx.x & 63;
    int w = word[r];
    const float4* src = (const float4*)(emb + (size_t)w * EMB);
    float4* dst = (float4*)(out + (size_t)r * EMB);
    uint2* dsth = (uint2*)(out_h + (size_t)r * EMB);
    float4 v[4];
#pragma unroll
    for (int k = 0; k < 4; k++) v[k] = src[c + k * 64];
#pragma unroll
    for (int k = 0; k < 4; k++) {
        dst[c + k * 64] = v[k];
        dsth[c + k * 64] = f4_to_h4(v[k]);
    }
}

// ---------------- pipelined fp16 NT GEMM: C = A*B^T + bias -------------------
// blockIdx.z selects operand set (B,bias,C) vs (B2,bias2,C2): lets two GEMMs
// sharing the same A run as ONE launch (better wave packing).
#define PSTAGES 3
#define HSTRIDE 40                       // halves per tile row (32 data + 8 pad)
#define HTILE   (128 * HSTRIDE)          // 5120 halves per tile
#define GEMM_SMEM (PSTAGES * 2 * HTILE * 2)   // 61440 bytes

__global__ __launch_bounds__(256, 2)
void gemm_f16_pipe(const __half* __restrict__ A, const __half* __restrict__ B,
                   const float* __restrict__ bias, float* __restrict__ C,
                   const __half* __restrict__ B2, const float* __restrict__ bias2,
                   float* __restrict__ C2,
                   int M, int N, int K, int swap) {
    if (blockIdx.z == 1) { B = B2; bias = bias2; C = C2; }
    extern __shared__ __half smh[];
    __half* As = smh;                      // [PSTAGES][128][HSTRIDE]
    __half* Bs = smh + PSTAGES * HTILE;

    int tid = threadIdx.x;
    int bn = (swap ? blockIdx.y : blockIdx.x) * 128;
    int bm = (swap ? blockIdx.x : blockIdx.y) * 128;
    int wid = tid >> 5, lane = tid & 31;
    int wm = wid & 3;
    int wn = wid >> 2;
    int grp = lane >> 2;
    int tig = lane & 3;

    int r0 = tid >> 2, c0 = (tid & 3) << 3;      // chunk tid
    int r1 = r0 + 64, c1 = c0;                   // chunk tid+256
    const __half* Ab = A + (size_t)bm * K;
    const __half* Bb = B + (size_t)bn * K;

    float acc[2][8][4];
#pragma unroll
    for (int i = 0; i < 2; i++)
#pragma unroll
        for (int j = 0; j < 8; j++)
#pragma unroll
            for (int q = 0; q < 4; q++) acc[i][j][q] = 0.f;

    int KT = K >> 5;

#pragma unroll
    for (int s = 0; s < PSTAGES - 1; s++) {
        int k0 = s * 32;
        cp_async16(&As[s * HTILE + r0 * HSTRIDE + c0], Ab + (size_t)r0 * K + k0 + c0);
        cp_async16(&As[s * HTILE + r1 * HSTRIDE + c1], Ab + (size_t)r1 * K + k0 + c1);
        cp_async16(&Bs[s * HTILE + r0 * HSTRIDE + c0], Bb + (size_t)r0 * K + k0 + c0);
        cp_async16(&Bs[s * HTILE + r1 * HSTRIDE + c1], Bb + (size_t)r1 * K + k0 + c1);
        asm volatile("cp.async.commit_group;");
    }

    for (int kt = 0; kt < KT; kt++) {
        asm volatile("cp.async.wait_group %0;" :: "n"(PSTAGES - 2));
        __syncthreads();

        const __half* Ast = &As[(kt % PSTAGES) * HTILE];
        const __half* Bst = &Bs[(kt % PSTAGES) * HTILE];

#pragma unroll
        for (int ks = 0; ks < 2; ks++) {
            int koff = ks * 16 + 2 * tig;
            uint32_t af[2][4];
#pragma unroll
            for (int i = 0; i < 2; i++) {
                int mr = wm * 32 + i * 16 + grp;
                af[i][0] = *(const uint32_t*)&Ast[mr * HSTRIDE + koff];
                af[i][1] = *(const uint32_t*)&Ast[(mr + 8) * HSTRIDE + koff];
                af[i][2] = *(const uint32_t*)&Ast[mr * HSTRIDE + koff + 8];
                af[i][3] = *(const uint32_t*)&Ast[(mr + 8) * HSTRIDE + koff + 8];
            }
            uint32_t bf[8][2];
#pragma unroll
            for (int j = 0; j < 8; j++) {
                int nc = wn * 64 + j * 8 + grp;
                bf[j][0] = *(const uint32_t*)&Bst[nc * HSTRIDE + koff];
                bf[j][1] = *(const uint32_t*)&Bst[nc * HSTRIDE + koff + 8];
            }
#pragma unroll
            for (int i = 0; i < 2; i++)
#pragma unroll
                for (int j = 0; j < 8; j++)
                    mma_f16(acc[i][j], af[i][0], af[i][1], af[i][2], af[i][3],
                            bf[j][0], bf[j][1]);
        }

        int nk = kt + PSTAGES - 1;
        if (nk < KT) {
            int st = nk % PSTAGES;
            int k0 = nk * 32;
            cp_async16(&As[st * HTILE + r0 * HSTRIDE + c0], Ab + (size_t)r0 * K + k0 + c0);
            cp_async16(&As[st * HTILE + r1 * HSTRIDE + c1], Ab + (size_t)r1 * K + k0 + c1);
            cp_async16(&Bs[st * HTILE + r0 * HSTRIDE + c0], Bb + (size_t)r0 * K + k0 + c0);
            cp_async16(&Bs[st * HTILE + r1 * HSTRIDE + c1], Bb + (size_t)r1 * K + k0 + c1);
        }
        asm volatile("cp.async.commit_group;");
    }

#pragma unroll
    for (int i = 0; i < 2; i++) {
        int row = bm + wm * 32 + i * 16 + grp;
#pragma unroll
        for (int j = 0; j < 8; j++) {
            int col = bn + wn * 64 + j * 8 + 2 * tig;
            float bsv0 = bias[col], bsv1 = bias[col + 1];
            float2 o0 = make_float2(acc[i][j][0] + bsv0, acc[i][j][1] + bsv1);
            float2 o1 = make_float2(acc[i][j][2] + bsv0, acc[i][j][3] + bsv1);
            *(float2*)(C + (size_t)row * N + col) = o0;
            *(float2*)(C + (size_t)(row + 8) * N + col) = o1;
        }
    }
}

// ---------------- software grid barrier (all NBLK blocks co-resident) --------
__device__ __forceinline__ void grid_barrier() {
    __syncthreads();
    if (threadIdx.x == 0) {
        volatile unsigned int* genp = &g_bar_gen;
        unsigned int gen = *genp;
        __threadfence();
        unsigned int rank = atomicAdd(&g_bar_count, 1u);
        if (rank == NBLK - 1) {
            g_bar_count = 0u;
            __threadfence();
            *genp = gen + 1u;
        } else {
            while (*genp == gen) { __nanosleep(16); }
        }
        __threadfence();
    }
    __syncthreads();
}

// ---------------- persistent recurrence v6: plain-fp16 W, 1-term HMMA --------
// R15 skeleton (256 blocks, 2 grid barriers/step, register-carried latent,
// fp16-shadow staging, prefetched epilogue operands). W rounded to fp16 —
// per R14 evidence, recurrence-side fp16 rounding is invisible at the output.
#define RW 136                            // smem row stride (halves)
#define REC6_SMEM ((64 * RW + 32 * RW) * 2)   // 26112 B

__global__ __launch_bounds__(256)
void ran_recurrence6(const float* __restrict__ Wi, const float* __restrict__ Wf,
                     const float* __restrict__ xi, const float* __restrict__ xf,
                     const float* __restrict__ xseq,
                     const float* __restrict__ lat0,
                     float* __restrict__ lats,
                     __half* __restrict__ lats_h,
                     float* __restrict__ part0, float* __restrict__ part1,
                     float* __restrict__ igout, float* __restrict__ fgout) {
    extern __shared__ __half sh[];
    __half* sW = sh;                      // [64][RW]  (32 gate-i rows + 32 gate-f)
    __half* sL = sh + 64 * RW;            // [32][RW]

    int tid = threadIdx.x;
    int gt = blockIdx.x & 31;
    int kc = blockIdx.x >> 5;
    int g0 = gt * 32;
    int k0 = kc * 128;
    int wid = tid >> 5, lane = tid & 31;
    int wm = wid & 3, wn = wid >> 2;
    int grp = lane >> 2, tig = lane & 3;

    // ---- load W once as fp16: 64 rows (32 gate-i + 32 gate-f) x 128 k ----
    for (int i = tid; i < 2048; i += 256) {         // 2048 float4 chunks
        int row = i >> 5, c4 = i & 31;
        const float* src = (row < 32)
            ? (Wi + (size_t)(g0 + row) * HID + k0 + c4 * 4)
            : (Wf + (size_t)(g0 + row - 32) * HID + k0 + c4 * 4);
        float4 v = *(const float4*)src;
        int off = row * RW + c4 * 4;
        *(__half2*)&sW[off]     = __floats2half2_rn(v.x, v.y);
        *(__half2*)&sW[off + 2] = __floats2half2_rn(v.z, v.w);
    }

    const __half* Aw = sW + (16 * wm + grp) * RW;

    // epilogue thread->output mapping is constant across steps
    int p = blockIdx.x * 128 + tid;       // valid for tid < 128
    int eg = p >> 5, eb = p & 31;
    int eidx = eb * HID + eg;
    float lstate = 0.f;
    if (tid < 128) lstate = __ldcg(lat0 + eidx);   // register-carried latent

    for (int s = 0; s < S_LEN; s++) {
        // ---- stage lat tile [32 b][128 k] as fp16 ----
        if (s == 0) {
            for (int i = tid; i < 1024; i += 256) {
                int b = i >> 5, kq = i & 31;
                float4 v = __ldcg((const float4*)(lat0 + (size_t)b * HID + k0 + kq * 4));
                int off = b * RW + kq * 4;
                *(__half2*)&sL[off]     = __floats2half2_rn(v.x, v.y);
                *(__half2*)&sL[off + 2] = __floats2half2_rn(v.z, v.w);
            }
        } else {
            const __half* lsrc = lats_h + (size_t)(s - 1) * BH;
            for (int i = tid; i < 512; i += 256) {       // 512 x 16B chunks
                int b = i >> 4, kq = i & 15;
                uint4 v = __ldcg((const uint4*)(lsrc + (size_t)b * HID + k0 + kq * 8));
                *(uint4*)&sL[b * RW + kq * 8] = v;
            }
        }

        // ---- prefetch epilogue operands (independent of partials/barrier) ----
        float pre_xi = 0.f, pre_xf = 0.f, pre_x = 0.f;
        size_t sidx = (size_t)s * BH + eidx;
        if (tid < 128) {
            pre_xi = __ldcg(xi + sidx);
            pre_xf = __ldcg(xf + sidx);
            pre_x  = __ldcg(xseq + sidx);
        }
        __syncthreads();

        // ---- split-K gate GEMM via HMMA: warp tile m16 x n16 (2 n-tiles) ----
        float acc[2][4];
#pragma unroll
        for (int jj = 0; jj < 2; jj++)
#pragma unroll
            for (int q = 0; q < 4; q++) acc[jj][q] = 0.f;

#pragma unroll
        for (int ks = 0; ks < 8; ks++) {
            int kb = ks * 16 + 2 * tig;
            uint32_t a0 = *(const uint32_t*)&Aw[kb];
            uint32_t a1 = *(const uint32_t*)&Aw[8 * RW + kb];
            uint32_t a2 = *(const uint32_t*)&Aw[kb + 8];
            uint32_t a3 = *(const uint32_t*)&Aw[8 * RW + kb + 8];
#pragma unroll
            for (int jj = 0; jj < 2; jj++) {
                int brow = (16 * wn + 8 * jj + grp) * RW;
                uint32_t b0 = *(const uint32_t*)&sL[brow + kb];
                uint32_t b1 = *(const uint32_t*)&sL[brow + kb + 8];
                mma_f16(acc[jj], a0, a1, a2, a3, b0, b1);
            }
        }

        // ---- write partials (same [kc][g*32+b] layout as R4) ----
        int row0 = 16 * wm + grp;
#pragma unroll
        for (int jj = 0; jj < 2; jj++) {
            int bcol = 16 * wn + 8 * jj + 2 * tig;
            {
                int r = row0;
                float* pp = (r < 32) ? part0 : part1;
                int gg = g0 + (r & 31);
                pp[kc * BH + gg * 32 + bcol]     = acc[jj][0];
                pp[kc * BH + gg * 32 + bcol + 1] = acc[jj][1];
            }
            {
                int r = row0 + 8;
                float* pp = (r < 32) ? part0 : part1;
                int gg = g0 + (r & 31);
                pp[kc * BH + gg * 32 + bcol]     = acc[jj][2];
                pp[kc * BH + gg * 32 + bcol + 1] = acc[jj][3];
            }
        }

        grid_barrier();

        // ---- epilogue: reduce + sigmoid + state update ----
        if (tid < 128) {
            float ci = 0.f, cf = 0.f;
#pragma unroll
            for (int q = 0; q < 8; q++) {
                ci += __ldcg(&part0[q * BH + p]);
                cf += __ldcg(&part1[q * BH + p]);
            }
            float ig = 1.f / (1.f + __expf(-(ci + pre_xi)));
            float fg = 1.f / (1.f + __expf(-(cf + pre_xf)));
            float nl = ig * pre_x + fg * lstate;
            lstate = nl;
            lats[sidx] = nl;
            lats_h[sidx] = __float2half_rn(nl);
            if (s == S_LEN - 1 && igout) {
                igout[eidx] = ig;
                fgout[eidx] = fg;
            }
        }

        if (s != S_LEN - 1) grid_barrier();
    }
}

// ---------------- host orchestration ----------------
extern "C" void kernel_launch(void* const* d_in, const int* in_sizes, int n_in,
                              void* d_out, int out_size) {
    const int*   word    = (const int*)d_in[0];
    const float* latent0 = (const float*)d_in[1];
    const float* emb     = (const float*)d_in[2];
    const float* h2o_w   = (const float*)d_in[3];
    const float* h2o_b   = (const float*)d_in[4];
    const float* Whi     = (const float*)d_in[5];
    const float* Wxi_w   = (const float*)d_in[6];
    const float* Wxi_b   = (const float*)d_in[7];
    const float* Whf     = (const float*)d_in[8];
    const float* Wxf_w   = (const float*)d_in[9];
    const float* Wxf_b   = (const float*)d_in[10];
    const float* Whi2    = (const float*)d_in[11];
    const float* Wxi2_w  = (const float*)d_in[12];
    const float* Wxi2_b  = (const float*)d_in[13];
    const float* Whf2    = (const float*)d_in[14];
    const float* Wxf2_w  = (const float*)d_in[15];
    const float* Wxf2_b  = (const float*)d_in[16];
    float* out = (float*)d_out;

    float *embeds, *xi1, *xf1, *xi2, *xf2, *lats1, *lats2, *p0, *p1;
    __half *embeds_h, *lats1_h, *lats2_h, *h2o_h, *wx_h;
    cudaGetSymbolAddress((void**)&embeds, g_embeds);
    cudaGetSymbolAddress((void**)&embeds_h, g_embeds_h);
    cudaGetSymbolAddress((void**)&xi1, g_xi1);
    cudaGetSymbolAddress((void**)&xf1, g_xf1);
    cudaGetSymbolAddress((void**)&xi2, g_xi2);
    cudaGetSymbolAddress((void**)&xf2, g_xf2);
    cudaGetSymbolAddress((void**)&lats1, g_lats1);
    cudaGetSymbolAddress((void**)&lats1_h, g_lats1_h);
    cudaGetSymbolAddress((void**)&lats2, g_lats2);
    cudaGetSymbolAddress((void**)&lats2_h, g_lats2_h);
    cudaGetSymbolAddress((void**)&p0, g_part0);
    cudaGetSymbolAddress((void**)&p1, g_part1);
    cudaGetSymbolAddress((void**)&h2o_h, g_h2o_h);
    cudaGetSymbolAddress((void**)&wx_h, g_wx_h);

    static bool attr_done = false;
    if (!attr_done) {
        cudaFuncSetAttribute(ran_recurrence6,
                             cudaFuncAttributeMaxDynamicSharedMemorySize, REC6_SMEM);
        cudaFuncSetAttribute(gemm_f16_pipe,
                             cudaFuncAttributeMaxDynamicSharedMemorySize, GEMM_SMEM);
        attr_done = true;
    }

    // output layout (reference return order): latent | logits | ig_last | fg_last
    float* out_latent = out;
    float* out_logits = out + BH;
    float* out_ig     = out + (size_t)BH + (size_t)SB * VOCAB;
    float* out_fg     = out_ig + BH;

    __half* wxi_h  = wx_h;
    __half* wxf_h  = wx_h + (size_t)HID * EMB;
    __half* wxi2_h = wx_h + 2 * (size_t)HID * EMB;
    __half* wxf2_h = wx_h + 3 * (size_t)HID * EMB;

    // 0) fp16 pre-conversion of batched-GEMM weights (MLP-4 convert kernels)
    {
        int n4w = (int)((size_t)VOCAB * HID / 4);
        to_f16_kernel<<<(n4w + 1023) / 1024, 256>>>(h2o_w, h2o_h, n4w);
        int n4 = HID * EMB / 4;
        to_f16_kernel<<<(n4 + 1023) / 1024, 256>>>(Wxi_w, wxi_h, n4);
        to_f16_kernel<<<(n4 + 1023) / 1024, 256>>>(Wxf_w, wxf_h, n4);
        to_f16_kernel<<<(n4 + 1023) / 1024, 256>>>(Wxi2_w, wxi2_h, n4);
        to_f16_kernel<<<(n4 + 1023) / 1024, 256>>>(Wxf2_w, wxf2_h, n4);
    }

    // 1) embedding gather (fp32 + fp16 copies, 4 rows/block)
    embed_gather<<<SB / 4, 256>>>(word, emb, embeds, embeds_h);

    // 2) layer-1 xi+xf pre-activations: ONE launch, z selects gate
    {
        dim3 grid(HID / 128, SB / 128, 2);
        gemm_f16_pipe<<<grid, 256, GEMM_SMEM>>>(embeds_h, wxi_h, Wxi_b, xi1,
                                                wxf_h, Wxf_b, xf1,
                                                SB, HID, EMB, 0);
    }

    // 3) layer-1 recurrence (persistent, plain-fp16 W HMMA)
    ran_recurrence6<<<NBLK, 256, REC6_SMEM>>>(Whi, Whf, xi1, xf1, embeds, latent0,
                                              lats1, lats1_h, p0, p1,
                                              nullptr, nullptr);

    // 4) layer-2 xi+xf pre-activations (input = l1_out): ONE launch
    {
        dim3 grid(HID / 128, SB / 128, 2);
        gemm_f16_pipe<<<grid, 256, GEMM_SMEM>>>(lats1_h, wxi2_h, Wxi2_b, xi2,
                                                wxf2_h, Wxf2_b, xf2,
                                                SB, HID, EMB, 0);
    }

    // 5) layer-2 recurrence (initial latent = layer-1 final latent)
    ran_recurrence6<<<NBLK, 256, REC6_SMEM>>>(Whi2, Whf2, xi2, xf2, lats1,
                                              lats1 + (size_t)(S_LEN - 1) * BH,
                                              lats2, lats2_h, p0, p1,
                                              out_ig, out_fg);

    // 6) final latent copy
    cudaMemcpyAsync(out_latent, lats2 + (size_t)(S_LEN - 1) * BH,
                    BH * sizeof(float), cudaMemcpyDeviceToDevice);

    // 7) logits = l2_out @ h2o_w^T + h2o_b  (fp16 mma.sync, m-fastest grid)
    {
        dim3 grid(SB / 128, VOCAB / 128, 1);
        gemm_f16_pipe<<<grid, 256, GEMM_SMEM>>>(lats2_h, h2o_h, h2o_b, out_logits,
                                                h2o_h, h2o_b, out_logits,
                                                SB, VOCAB, HID, 1);
    }

    (void)in_sizes; (void)n_in; (void)out_size;
}